// round 7
// baseline (speedup 1.0000x reference)
#include <cuda_runtime.h>

// Problem constants (fixed shapes)
#define B_   2
#define S_   2048
#define D_   1024
#define H_   16
#define HD_  64
#define M_TOT (B_ * S_)   // 4096

// ---------------------------------------------------------------------------
// Scratch buffers. g_q/g_k/g_v hold tf32-ROUNDED bit patterns (Q pre-scaled
// by 1/sqrt(HD)); g_att is plain fp32.
// ---------------------------------------------------------------------------
__device__ float g_q[B_ * H_ * S_ * HD_];    // [B,H,S,HD]
__device__ float g_k[B_ * H_ * S_ * HD_];
__device__ float g_v[B_ * H_ * S_ * HD_];
__device__ float g_att[B_ * S_ * D_];        // [B,S,D]

// ---------------------------------------------------------------------------
// Helpers
// ---------------------------------------------------------------------------
__device__ __forceinline__ unsigned f2tf(float x) {
    unsigned u;
    asm("cvt.rna.tf32.f32 %0, %1;" : "=r"(u) : "f"(x));
    return u;
}

__device__ __forceinline__ void mma_tf32(float* d, const unsigned* a,
                                         unsigned b0, unsigned b1) {
    asm volatile(
        "mma.sync.aligned.m16n8k8.row.col.f32.tf32.tf32.f32 "
        "{%0,%1,%2,%3}, {%4,%5,%6,%7}, {%8,%9}, {%0,%1,%2,%3};"
        : "+f"(d[0]), "+f"(d[1]), "+f"(d[2]), "+f"(d[3])
        : "r"(a[0]), "r"(a[1]), "r"(a[2]), "r"(a[3]), "r"(b0), "r"(b1));
}

__device__ __forceinline__ void cp_async16(void* smem_dst, const void* gmem_src) {
    unsigned saddr = (unsigned)__cvta_generic_to_shared(smem_dst);
    asm volatile("cp.async.cg.shared.global [%0], [%1], 16;"
                 :: "r"(saddr), "l"(gmem_src));
}

// ---------------------------------------------------------------------------
// Pipelined TF32 GEMM core (R3 proven). Templated by a thin wrapper below.
// CTA tile 128x128x32, 8 warps (2x4), warp tile 64x32, register prefetch.
// ---------------------------------------------------------------------------
#define GBM 128
#define GBN 128
#define GBK 32
#define GASTR 36
#define GBSTR 136

__device__ __forceinline__ void gemm_body(
    const float* __restrict__ A, const float* __restrict__ W,
    const float* __restrict__ bias, float* __restrict__ out,
    int M, int N, int K, int qkv_mode, float oscale,
    float* As, float* Bs)
{
    const int tid  = threadIdx.x;
    const int warp = tid >> 5;
    const int lane = tid & 31;
    const int g    = lane >> 2;
    const int tig  = lane & 3;
    const int wm   = (warp >> 2) * 64;
    const int wn   = (warp & 3) * 32;
    const int bm   = blockIdx.y * GBM;
    const int bn   = blockIdx.x * GBN;

    const int arow = tid >> 1;
    const int acol = (tid & 1) * 16;
    const int brow = tid >> 3;
    const int bcol = (tid & 7) * 16;

    float acc[16][4];
#pragma unroll
    for (int f = 0; f < 16; f++)
#pragma unroll
        for (int e = 0; e < 4; e++) acc[f][e] = 0.0f;

    const float* Aro = A + (size_t)(bm + arow) * K + acol;
    const float* Bro = W + (size_t)brow * N + bn + bcol;

    float4 ra[4], rb[4];

#pragma unroll
    for (int p = 0; p < 4; p++) ra[p] = *(const float4*)(Aro + p * 4);
#pragma unroll
    for (int p = 0; p < 4; p++) rb[p] = *(const float4*)(Bro + p * 4);
#pragma unroll
    for (int p = 0; p < 4; p++) {
        uint4 t = { f2tf(ra[p].x), f2tf(ra[p].y), f2tf(ra[p].z), f2tf(ra[p].w) };
        *(uint4*)(As + arow * GASTR + acol + p * 4) = t;
        uint4 u = { f2tf(rb[p].x), f2tf(rb[p].y), f2tf(rb[p].z), f2tf(rb[p].w) };
        *(uint4*)(Bs + brow * GBSTR + bcol + p * 4) = u;
    }
    __syncthreads();

    const int NT = K / GBK;
    for (int t = 0; t < NT; t++) {
        if (t + 1 < NT) {
            const float* An = Aro + (t + 1) * GBK;
            const float* Bn = Bro + (size_t)(t + 1) * GBK * N;
#pragma unroll
            for (int p = 0; p < 4; p++) ra[p] = *(const float4*)(An + p * 4);
#pragma unroll
            for (int p = 0; p < 4; p++) rb[p] = *(const float4*)(Bn + p * 4);
        }

#pragma unroll
        for (int kk = 0; kk < GBK; kk += 8) {
            unsigned af[4][4];
#pragma unroll
            for (int i = 0; i < 4; i++) {
                const float* base = As + (wm + i * 16 + g) * GASTR + kk + tig;
                af[i][0] = __float_as_uint(base[0]);
                af[i][1] = __float_as_uint(base[8 * GASTR]);
                af[i][2] = __float_as_uint(base[4]);
                af[i][3] = __float_as_uint(base[8 * GASTR + 4]);
            }
            unsigned bf[4][2];
#pragma unroll
            for (int j = 0; j < 4; j++) {
                bf[j][0] = __float_as_uint(Bs[(kk + tig) * GBSTR + wn + j * 8 + g]);
                bf[j][1] = __float_as_uint(Bs[(kk + tig + 4) * GBSTR + wn + j * 8 + g]);
            }
#pragma unroll
            for (int i = 0; i < 4; i++)
#pragma unroll
                for (int j = 0; j < 4; j++)
                    mma_tf32(acc[i * 4 + j], af[i], bf[j][0], bf[j][1]);
        }
        __syncthreads();

        if (t + 1 < NT) {
#pragma unroll
            for (int p = 0; p < 4; p++) {
                uint4 ta = { f2tf(ra[p].x), f2tf(ra[p].y), f2tf(ra[p].z), f2tf(ra[p].w) };
                *(uint4*)(As + arow * GASTR + acol + p * 4) = ta;
                uint4 tb = { f2tf(rb[p].x), f2tf(rb[p].y), f2tf(rb[p].z), f2tf(rb[p].w) };
                *(uint4*)(Bs + brow * GBSTR + bcol + p * 4) = tb;
            }
            __syncthreads();
        }
    }

#pragma unroll
    for (int i = 0; i < 4; i++) {
#pragma unroll
        for (int j = 0; j < 4; j++) {
            const float* d = acc[i * 4 + j];
            int col = bn + wn + j * 8 + 2 * tig;
            float2 b2 = *(const float2*)(bias + col);
            int row_lo = bm + wm + i * 16 + g;
            float2 vlo = { d[0] + b2.x, d[1] + b2.y };
            float2 vhi = { d[2] + b2.x, d[3] + b2.y };
            if (qkv_mode) {
                uint2 tlo = { f2tf(vlo.x * oscale), f2tf(vlo.y * oscale) };
                uint2 thi = { f2tf(vhi.x * oscale), f2tf(vhi.y * oscale) };
                int h = col / HD_, dd = col % HD_;
                int b0i = row_lo / S_, s0 = row_lo % S_;
                *(uint2*)(out + ((size_t)((b0i * H_ + h) * S_ + s0)) * HD_ + dd) = tlo;
                int row_hi = row_lo + 8;
                int b1i = row_hi / S_, s1 = row_hi % S_;
                *(uint2*)(out + ((size_t)((b1i * H_ + h) * S_ + s1)) * HD_ + dd) = thi;
            } else {
                *(float2*)(out + (size_t)row_lo * N + col) = vlo;
                *(float2*)(out + (size_t)(row_lo + 8) * N + col) = vhi;
            }
        }
    }
}

// Fused QKV: grid.z in {0,1,2} selects projection.
__global__ void __launch_bounds__(256, 2) gemm_qkv_kernel(
    const float* __restrict__ x,
    const float* __restrict__ Wq, const float* __restrict__ bq, float* __restrict__ oq,
    const float* __restrict__ Wk, const float* __restrict__ bk, float* __restrict__ ok,
    const float* __restrict__ Wv, const float* __restrict__ bv, float* __restrict__ ov)
{
    __shared__ float As[GBM * GASTR];
    __shared__ float Bs[GBK * GBSTR];
    const int z = blockIdx.z;
    const float* W  = (z == 0) ? Wq : (z == 1) ? Wk : Wv;
    const float* bb = (z == 0) ? bq : (z == 1) ? bk : bv;
    float* o        = (z == 0) ? oq : (z == 1) ? ok : ov;
    float osc       = (z == 0) ? 0.125f : 1.0f;
    gemm_body(x, W, bb, o, M_TOT, D_, D_, 1, osc, As, Bs);
}

// Output projection.
__global__ void __launch_bounds__(256, 2) gemm_out_kernel(
    const float* __restrict__ A, const float* __restrict__ W,
    const float* __restrict__ bias, float* __restrict__ out)
{
    __shared__ float As[GBM * GASTR];
    __shared__ float Bs[GBK * GBSTR];
    gemm_body(A, W, bias, out, M_TOT, D_, D_, 0, 1.0f, As, Bs);
}

// ---------------------------------------------------------------------------
// Flash attention v6: 8 warps, Q tile 128 (16 rows/warp), KV tile 64,
// cp.async double buffer; Q/K/V arrive as ready tf32 bits.
// ---------------------------------------------------------------------------
#define AQ  128
#define AKV 64
#define AST 68
#define ATILE (AKV * AST)

extern __shared__ float attn_sm[];

__global__ void __launch_bounds__(256) attn_kernel(
    const float* __restrict__ Qb, const float* __restrict__ Kb,
    const float* __restrict__ Vb, float* __restrict__ Ob)
{
    float* Ks0 = attn_sm;
    float* Vs0 = attn_sm + ATILE;
    float* Ks1 = attn_sm + 2 * ATILE;
    float* Vs1 = attn_sm + 3 * ATILE;

    const int bh   = blockIdx.y;
    const int qt   = blockIdx.x;
    const int tid  = threadIdx.x;
    const int warp = tid >> 5;          // 0..7
    const int lane = tid & 31;
    const int g    = lane >> 2;
    const int tig  = lane & 3;

    // cp.async mapping: 256 threads cover 64x64 tile, 4 rows each
    const int lr = tid >> 4;            // 0..15
    const int lc = (tid & 15) * 4;      // 0..60

    const float* Kbase = Kb + (size_t)bh * S_ * HD_;
    const float* Vbase = Vb + (size_t)bh * S_ * HD_;

    // Prologue: tile 0
    {
#pragma unroll
        for (int i = 0; i < 4; i++) {
            int r = i * 16 + lr;
            cp_async16(Ks0 + r * AST + lc, Kbase + (size_t)r * HD_ + lc);
            cp_async16(Vs0 + r * AST + lc, Vbase + (size_t)r * HD_ + lc);
        }
        asm volatile("cp.async.commit_group;");
    }

    // Q fragments: raw tf32 bits (pre-scaled by 0.125)
    const int qrow0 = qt * AQ + warp * 16;
    const float* Qp = Qb + ((size_t)bh * S_ + qrow0) * HD_;
    unsigned qa[8][4];
#pragma unroll
    for (int kc = 0; kc < 8; kc++) {
        int c0 = kc * 8 + tig;
        qa[kc][0] = __float_as_uint(Qp[(size_t)g * HD_ + c0]);
        qa[kc][1] = __float_as_uint(Qp[(size_t)(g + 8) * HD_ + c0]);
        qa[kc][2] = __float_as_uint(Qp[(size_t)g * HD_ + c0 + 4]);
        qa[kc][3] = __float_as_uint(Qp[(size_t)(g + 8) * HD_ + c0 + 4]);
    }

    float o[8][4];
#pragma unroll
    for (int j = 0; j < 8; j++)
#pragma unroll
        for (int e = 0; e < 4; e++) o[j][e] = 0.0f;
    float m_lo = -1e30f, m_hi = -1e30f;
    float l_lo = 0.0f,   l_hi = 0.0f;

    const unsigned FULL = 0xffffffffu;
    const int src0 = (lane & ~3) | (tig >> 1);
    const int src1 = src0 + 2;

    const int NT = S_ / AKV;
    for (int kt = 0; kt < NT; kt++) {
        if (kt + 1 < NT) {
            float* Kd = (kt & 1) ? Ks0 : Ks1;
            float* Vd = (kt & 1) ? Vs0 : Vs1;
            const float* Kp = Kbase + (size_t)(kt + 1) * AKV * HD_;
            const float* Vp = Vbase + (size_t)(kt + 1) * AKV * HD_;
#pragma unroll
            for (int i = 0; i < 4; i++) {
                int r = i * 16 + lr;
                cp_async16(Kd + r * AST + lc, Kp + (size_t)r * HD_ + lc);
                cp_async16(Vd + r * AST + lc, Vp + (size_t)r * HD_ + lc);
            }
            asm volatile("cp.async.commit_group;");
            asm volatile("cp.async.wait_group 1;");
        } else {
            asm volatile("cp.async.wait_group 0;");
        }
        __syncthreads();

        const float* Ks = (kt & 1) ? Ks1 : Ks0;
        const float* Vs = (kt & 1) ? Vs1 : Vs0;

        // ---- S = Qs @ K^T ----
        float s[8][4];
#pragma unroll
        for (int j = 0; j < 8; j++)
#pragma unroll
            for (int e = 0; e < 4; e++) s[j][e] = 0.0f;

#pragma unroll
        for (int kc = 0; kc < 8; kc++) {
            int c0 = kc * 8 + tig;
#pragma unroll
            for (int j = 0; j < 8; j++) {
                unsigned b0 = __float_as_uint(Ks[(j * 8 + g) * AST + c0]);
                unsigned b1 = __float_as_uint(Ks[(j * 8 + g) * AST + c0 + 4]);
                mma_tf32(s[j], qa[kc], b0, b1);
            }
        }

        // ---- Online softmax ----
        float mx_lo = -1e30f, mx_hi = -1e30f;
#pragma unroll
        for (int j = 0; j < 8; j++) {
            mx_lo = fmaxf(mx_lo, fmaxf(s[j][0], s[j][1]));
            mx_hi = fmaxf(mx_hi, fmaxf(s[j][2], s[j][3]));
        }
        mx_lo = fmaxf(mx_lo, __shfl_xor_sync(FULL, mx_lo, 1));
        mx_lo = fmaxf(mx_lo, __shfl_xor_sync(FULL, mx_lo, 2));
        mx_hi = fmaxf(mx_hi, __shfl_xor_sync(FULL, mx_hi, 1));
        mx_hi = fmaxf(mx_hi, __shfl_xor_sync(FULL, mx_hi, 2));

        float mn_lo = fmaxf(m_lo, mx_lo);
        float mn_hi = fmaxf(m_hi, mx_hi);
        float al_lo = __expf(m_lo - mn_lo);
        float al_hi = __expf(m_hi - mn_hi);
        m_lo = mn_lo; m_hi = mn_hi;

        float sum_lo = 0.0f, sum_hi = 0.0f;
#pragma unroll
        for (int j = 0; j < 8; j++) {
            float p0 = __expf(s[j][0] - mn_lo);
            float p1 = __expf(s[j][1] - mn_lo);
            float p2 = __expf(s[j][2] - mn_hi);
            float p3 = __expf(s[j][3] - mn_hi);
            sum_lo += p0 + p1;
            sum_hi += p2 + p3;
            s[j][0] = __uint_as_float(f2tf(p0));
            s[j][1] = __uint_as_float(f2tf(p1));
            s[j][2] = __uint_as_float(f2tf(p2));
            s[j][3] = __uint_as_float(f2tf(p3));
        }
        sum_lo += __shfl_xor_sync(FULL, sum_lo, 1);
        sum_lo += __shfl_xor_sync(FULL, sum_lo, 2);
        sum_hi += __shfl_xor_sync(FULL, sum_hi, 1);
        sum_hi += __shfl_xor_sync(FULL, sum_hi, 2);
        l_lo = l_lo * al_lo + sum_lo;
        l_hi = l_hi * al_hi + sum_hi;

#pragma unroll
        for (int j = 0; j < 8; j++) {
            o[j][0] *= al_lo; o[j][1] *= al_lo;
            o[j][2] *= al_hi; o[j][3] *= al_hi;
        }

        // ---- O += P @ V ----
#pragma unroll
        for (int kc = 0; kc < 8; kc++) {
            float v00 = __shfl_sync(FULL, s[kc][0], src0);
            float v01 = __shfl_sync(FULL, s[kc][1], src0);
            float v20 = __shfl_sync(FULL, s[kc][2], src0);
            float v21 = __shfl_sync(FULL, s[kc][3], src0);
            float w00 = __shfl_sync(FULL, s[kc][0], src1);
            float w01 = __shfl_sync(FULL, s[kc][1], src1);
            float w20 = __shfl_sync(FULL, s[kc][2], src1);
            float w21 = __shfl_sync(FULL, s[kc][3], src1);
            unsigned pa[4];
            pa[0] = __float_as_uint((tig & 1) ? v01 : v00);
            pa[1] = __float_as_uint((tig & 1) ? v21 : v20);
            pa[2] = __float_as_uint((tig & 1) ? w01 : w00);
            pa[3] = __float_as_uint((tig & 1) ? w21 : w20);

            int r0 = (kc * 8 + tig) * AST;
            int r1 = (kc * 8 + tig + 4) * AST;
#pragma unroll
            for (int jn = 0; jn < 8; jn++) {
                unsigned b0 = __float_as_uint(Vs[r0 + jn * 8 + g]);
                unsigned b1 = __float_as_uint(Vs[r1 + jn * 8 + g]);
                mma_tf32(o[jn], pa, b0, b1);
            }
        }
        __syncthreads();
    }

    float inv_lo = 1.0f / l_lo;
    float inv_hi = 1.0f / l_hi;
    int b = bh / H_, h = bh % H_;
    float* orow_lo = Ob + ((size_t)(b * S_ + qrow0 + g)) * D_ + h * HD_;
    float* orow_hi = Ob + ((size_t)(b * S_ + qrow0 + g + 8)) * D_ + h * HD_;
#pragma unroll
    for (int jn = 0; jn < 8; jn++) {
        float2 wlo = { o[jn][0] * inv_lo, o[jn][1] * inv_lo };
        float2 whi = { o[jn][2] * inv_hi, o[jn][3] * inv_hi };
        *(float2*)(orow_lo + jn * 8 + 2 * tig) = wlo;
        *(float2*)(orow_hi + jn * 8 + 2 * tig) = whi;
    }
}

// ---------------------------------------------------------------------------
// Launch
// ---------------------------------------------------------------------------
extern "C" void kernel_launch(void* const* d_in, const int* in_sizes, int n_in,
                              void* d_out, int out_size)
{
    (void)in_sizes; (void)n_in; (void)out_size;
    const float* x  = (const float*)d_in[0];
    const float* Wq = (const float*)d_in[1];
    const float* bq = (const float*)d_in[2];
    const float* Wk = (const float*)d_in[3];
    const float* bk = (const float*)d_in[4];
    const float* Wv = (const float*)d_in[5];
    const float* bv = (const float*)d_in[6];
    const float* Wo = (const float*)d_in[7];
    const float* bo = (const float*)d_in[8];
    float* out = (float*)d_out;

    void *pq, *pk, *pv, *patt;
    cudaGetSymbolAddress(&pq, g_q);
    cudaGetSymbolAddress(&pk, g_k);
    cudaGetSymbolAddress(&pv, g_v);
    cudaGetSymbolAddress(&patt, g_att);
    float* qb = (float*)pq;
    float* kb = (float*)pk;
    float* vb = (float*)pv;
    float* ab = (float*)patt;

    const int ATT_SMEM = 4 * ATILE * (int)sizeof(float);   // 69632 B
    cudaFuncSetAttribute(attn_kernel, cudaFuncAttributeMaxDynamicSharedMemorySize, ATT_SMEM);

    dim3 qkvgrid(D_ / GBN, M_TOT / GBM, 3);   // (8, 32, 3)
    gemm_qkv_kernel<<<qkvgrid, 256>>>(x, Wq, bq, qb, Wk, bk, kb, Wv, bv, vb);

    dim3 agrid(S_ / AQ, B_ * H_);             // (16, 32)
    attn_kernel<<<agrid, 256, ATT_SMEM>>>(qb, kb, vb, ab);

    dim3 ogrid(D_ / GBN, M_TOT / GBM);        // (8, 32)
    gemm_out_kernel<<<ogrid, 256>>>(ab, Wo, bo, out);
}

// round 8
// speedup vs baseline: 1.0732x; 1.0732x over previous
#include <cuda_runtime.h>

// Problem constants (fixed shapes)
#define B_   2
#define S_   2048
#define D_   1024
#define H_   16
#define HD_  64
#define M_TOT (B_ * S_)   // 4096

// ---------------------------------------------------------------------------
// Scratch buffers. g_q/g_k/g_v hold tf32-ROUNDED bit patterns (Q pre-scaled
// by 1/sqrt(HD)); g_att is plain fp32.
// ---------------------------------------------------------------------------
__device__ float g_q[B_ * H_ * S_ * HD_];    // [B,H,S,HD]
__device__ float g_k[B_ * H_ * S_ * HD_];
__device__ float g_v[B_ * H_ * S_ * HD_];
__device__ float g_att[B_ * S_ * D_];        // [B,S,D]

// ---------------------------------------------------------------------------
// Helpers
// ---------------------------------------------------------------------------
__device__ __forceinline__ unsigned f2tf(float x) {
    unsigned u;
    asm("cvt.rna.tf32.f32 %0, %1;" : "=r"(u) : "f"(x));
    return u;
}

__device__ __forceinline__ void mma_tf32(float* d, const unsigned* a,
                                         unsigned b0, unsigned b1) {
    asm volatile(
        "mma.sync.aligned.m16n8k8.row.col.f32.tf32.tf32.f32 "
        "{%0,%1,%2,%3}, {%4,%5,%6,%7}, {%8,%9}, {%0,%1,%2,%3};"
        : "+f"(d[0]), "+f"(d[1]), "+f"(d[2]), "+f"(d[3])
        : "r"(a[0]), "r"(a[1]), "r"(a[2]), "r"(a[3]), "r"(b0), "r"(b1));
}

__device__ __forceinline__ void cp_async16(void* smem_dst, const void* gmem_src) {
    unsigned saddr = (unsigned)__cvta_generic_to_shared(smem_dst);
    asm volatile("cp.async.cg.shared.global [%0], [%1], 16;"
                 :: "r"(saddr), "l"(gmem_src));
}

// ---------------------------------------------------------------------------
// Pipelined TF32 GEMM with DOUBLE-BUFFERED smem (one sync per K-tile).
// CTA tile 128x128x32, 8 warps (2x4), warp tile 64x32, register prefetch.
// ---------------------------------------------------------------------------
#define GBM 128
#define GBN 128
#define GBK 32
#define GASTR 36
#define GBSTR 136
#define ASZ (GBM * GASTR)   // 4608 floats
#define BSZ (GBK * GBSTR)   // 4352 floats

__global__ void __launch_bounds__(256, 2) gemm_tf32_kernel(
    const float* __restrict__ A, const float* __restrict__ W,
    const float* __restrict__ bias, float* __restrict__ out,
    int M, int N, int K, int qkv_mode, float oscale)
{
    __shared__ float As[2 * ASZ];   // 36 KB
    __shared__ float Bs[2 * BSZ];   // 34 KB

    const int tid  = threadIdx.x;
    const int warp = tid >> 5;
    const int lane = tid & 31;
    const int g    = lane >> 2;
    const int tig  = lane & 3;
    const int wm   = (warp >> 2) * 64;
    const int wn   = (warp & 3) * 32;
    const int bm   = blockIdx.y * GBM;
    const int bn   = blockIdx.x * GBN;

    const int arow = tid >> 1;
    const int acol = (tid & 1) * 16;
    const int brow = tid >> 3;
    const int bcol = (tid & 7) * 16;

    float acc[16][4];
#pragma unroll
    for (int f = 0; f < 16; f++)
#pragma unroll
        for (int e = 0; e < 4; e++) acc[f][e] = 0.0f;

    const float* Aro = A + (size_t)(bm + arow) * K + acol;
    const float* Bro = W + (size_t)brow * N + bn + bcol;

    float4 ra[4], rb[4];

    // ---- Prologue: tile 0 -> regs -> buffer 0 ----
#pragma unroll
    for (int p = 0; p < 4; p++) ra[p] = *(const float4*)(Aro + p * 4);
#pragma unroll
    for (int p = 0; p < 4; p++) rb[p] = *(const float4*)(Bro + p * 4);
#pragma unroll
    for (int p = 0; p < 4; p++) {
        uint4 t = { f2tf(ra[p].x), f2tf(ra[p].y), f2tf(ra[p].z), f2tf(ra[p].w) };
        *(uint4*)(As + arow * GASTR + acol + p * 4) = t;
        uint4 u = { f2tf(rb[p].x), f2tf(rb[p].y), f2tf(rb[p].z), f2tf(rb[p].w) };
        *(uint4*)(Bs + brow * GBSTR + bcol + p * 4) = u;
    }
    __syncthreads();

    const int NT = K / GBK;
    for (int t = 0; t < NT; t++) {
        // Prefetch next tile into registers
        if (t + 1 < NT) {
            const float* An = Aro + (t + 1) * GBK;
            const float* Bn = Bro + (size_t)(t + 1) * GBK * N;
#pragma unroll
            for (int p = 0; p < 4; p++) ra[p] = *(const float4*)(An + p * 4);
#pragma unroll
            for (int p = 0; p < 4; p++) rb[p] = *(const float4*)(Bn + p * 4);
        }

        const float* Ac = As + (t & 1) * ASZ;
        const float* Bc = Bs + (t & 1) * BSZ;

#pragma unroll
        for (int kk = 0; kk < GBK; kk += 8) {
            unsigned af[4][4];
#pragma unroll
            for (int i = 0; i < 4; i++) {
                const float* base = Ac + (wm + i * 16 + g) * GASTR + kk + tig;
                af[i][0] = __float_as_uint(base[0]);
                af[i][1] = __float_as_uint(base[8 * GASTR]);
                af[i][2] = __float_as_uint(base[4]);
                af[i][3] = __float_as_uint(base[8 * GASTR + 4]);
            }
            unsigned bf[4][2];
#pragma unroll
            for (int j = 0; j < 4; j++) {
                bf[j][0] = __float_as_uint(Bc[(kk + tig) * GBSTR + wn + j * 8 + g]);
                bf[j][1] = __float_as_uint(Bc[(kk + tig + 4) * GBSTR + wn + j * 8 + g]);
            }
#pragma unroll
            for (int i = 0; i < 4; i++)
#pragma unroll
                for (int j = 0; j < 4; j++)
                    mma_tf32(acc[i * 4 + j], af[i], bf[j][0], bf[j][1]);
        }

        // Store next tile into the OTHER buffer (safe: it was drained by the
        // end-of-previous-iteration barrier), then one sync.
        if (t + 1 < NT) {
            float* An2 = As + ((t + 1) & 1) * ASZ;
            float* Bn2 = Bs + ((t + 1) & 1) * BSZ;
#pragma unroll
            for (int p = 0; p < 4; p++) {
                uint4 ta = { f2tf(ra[p].x), f2tf(ra[p].y), f2tf(ra[p].z), f2tf(ra[p].w) };
                *(uint4*)(An2 + arow * GASTR + acol + p * 4) = ta;
                uint4 tb = { f2tf(rb[p].x), f2tf(rb[p].y), f2tf(rb[p].z), f2tf(rb[p].w) };
                *(uint4*)(Bn2 + brow * GBSTR + bcol + p * 4) = tb;
            }
            __syncthreads();
        }
    }

    // ---- Register epilogue ----
#pragma unroll
    for (int i = 0; i < 4; i++) {
#pragma unroll
        for (int j = 0; j < 4; j++) {
            const float* d = acc[i * 4 + j];
            int col = bn + wn + j * 8 + 2 * tig;
            float2 b2 = *(const float2*)(bias + col);
            int row_lo = bm + wm + i * 16 + g;
            float2 vlo = { d[0] + b2.x, d[1] + b2.y };
            float2 vhi = { d[2] + b2.x, d[3] + b2.y };
            if (qkv_mode) {
                uint2 tlo = { f2tf(vlo.x * oscale), f2tf(vlo.y * oscale) };
                uint2 thi = { f2tf(vhi.x * oscale), f2tf(vhi.y * oscale) };
                int h = col / HD_, dd = col % HD_;
                int b0i = row_lo / S_, s0 = row_lo % S_;
                *(uint2*)(out + ((size_t)((b0i * H_ + h) * S_ + s0)) * HD_ + dd) = tlo;
                int row_hi = row_lo + 8;
                int b1i = row_hi / S_, s1 = row_hi % S_;
                *(uint2*)(out + ((size_t)((b1i * H_ + h) * S_ + s1)) * HD_ + dd) = thi;
            } else {
                *(float2*)(out + (size_t)row_lo * N + col) = vlo;
                *(float2*)(out + (size_t)(row_lo + 8) * N + col) = vhi;
            }
        }
    }
}

// ---------------------------------------------------------------------------
// Flash attention (exact R6 version): 4 warps, Q tile 64, KV tile 64,
// cp.async double buffer; Q/K/V arrive as ready tf32 bits.
// ---------------------------------------------------------------------------
#define AQ  64
#define AKV 64
#define AST 68
#define ATILE (AKV * AST)

extern __shared__ float attn_sm[];

__global__ void __launch_bounds__(128) attn_kernel(
    const float* __restrict__ Qb, const float* __restrict__ Kb,
    const float* __restrict__ Vb, float* __restrict__ Ob)
{
    float* Ks0 = attn_sm;
    float* Vs0 = attn_sm + ATILE;
    float* Ks1 = attn_sm + 2 * ATILE;
    float* Vs1 = attn_sm + 3 * ATILE;

    const int bh   = blockIdx.y;
    const int qt   = blockIdx.x;
    const int tid  = threadIdx.x;
    const int warp = tid >> 5;
    const int lane = tid & 31;
    const int g    = lane >> 2;
    const int tig  = lane & 3;

    const int lr = tid >> 4;
    const int lc = (tid & 15) * 4;

    const float* Kbase = Kb + (size_t)bh * S_ * HD_;
    const float* Vbase = Vb + (size_t)bh * S_ * HD_;

    {
#pragma unroll
        for (int i = 0; i < 8; i++) {
            int r = i * 8 + lr;
            cp_async16(Ks0 + r * AST + lc, Kbase + (size_t)r * HD_ + lc);
            cp_async16(Vs0 + r * AST + lc, Vbase + (size_t)r * HD_ + lc);
        }
        asm volatile("cp.async.commit_group;");
    }

    const int qrow0 = qt * AQ + warp * 16;
    const float* Qp = Qb + ((size_t)bh * S_ + qrow0) * HD_;
    unsigned qa[8][4];
#pragma unroll
    for (int kc = 0; kc < 8; kc++) {
        int c0 = kc * 8 + tig;
        qa[kc][0] = __float_as_uint(Qp[(size_t)g * HD_ + c0]);
        qa[kc][1] = __float_as_uint(Qp[(size_t)(g + 8) * HD_ + c0]);
        qa[kc][2] = __float_as_uint(Qp[(size_t)g * HD_ + c0 + 4]);
        qa[kc][3] = __float_as_uint(Qp[(size_t)(g + 8) * HD_ + c0 + 4]);
    }

    float o[8][4];
#pragma unroll
    for (int j = 0; j < 8; j++)
#pragma unroll
        for (int e = 0; e < 4; e++) o[j][e] = 0.0f;
    float m_lo = -1e30f, m_hi = -1e30f;
    float l_lo = 0.0f,   l_hi = 0.0f;

    const unsigned FULL = 0xffffffffu;
    const int src0 = (lane & ~3) | (tig >> 1);
    const int src1 = src0 + 2;

    const int NT = S_ / AKV;
    for (int kt = 0; kt < NT; kt++) {
        if (kt + 1 < NT) {
            float* Kd = (kt & 1) ? Ks0 : Ks1;
            float* Vd = (kt & 1) ? Vs0 : Vs1;
            const float* Kp = Kbase + (size_t)(kt + 1) * AKV * HD_;
            const float* Vp = Vbase + (size_t)(kt + 1) * AKV * HD_;
#pragma unroll
            for (int i = 0; i < 8; i++) {
                int r = i * 8 + lr;
                cp_async16(Kd + r * AST + lc, Kp + (size_t)r * HD_ + lc);
                cp_async16(Vd + r * AST + lc, Vp + (size_t)r * HD_ + lc);
            }
            asm volatile("cp.async.commit_group;");
            asm volatile("cp.async.wait_group 1;");
        } else {
            asm volatile("cp.async.wait_group 0;");
        }
        __syncthreads();

        const float* Ks = (kt & 1) ? Ks1 : Ks0;
        const float* Vs = (kt & 1) ? Vs1 : Vs0;

        float s[8][4];
#pragma unroll
        for (int j = 0; j < 8; j++)
#pragma unroll
            for (int e = 0; e < 4; e++) s[j][e] = 0.0f;

#pragma unroll
        for (int kc = 0; kc < 8; kc++) {
            int c0 = kc * 8 + tig;
#pragma unroll
            for (int j = 0; j < 8; j++) {
                unsigned b0 = __float_as_uint(Ks[(j * 8 + g) * AST + c0]);
                unsigned b1 = __float_as_uint(Ks[(j * 8 + g) * AST + c0 + 4]);
                mma_tf32(s[j], qa[kc], b0, b1);
            }
        }

        float mx_lo = -1e30f, mx_hi = -1e30f;
#pragma unroll
        for (int j = 0; j < 8; j++) {
            mx_lo = fmaxf(mx_lo, fmaxf(s[j][0], s[j][1]));
            mx_hi = fmaxf(mx_hi, fmaxf(s[j][2], s[j][3]));
        }
        mx_lo = fmaxf(mx_lo, __shfl_xor_sync(FULL, mx_lo, 1));
        mx_lo = fmaxf(mx_lo, __shfl_xor_sync(FULL, mx_lo, 2));
        mx_hi = fmaxf(mx_hi, __shfl_xor_sync(FULL, mx_hi, 1));
        mx_hi = fmaxf(mx_hi, __shfl_xor_sync(FULL, mx_hi, 2));

        float mn_lo = fmaxf(m_lo, mx_lo);
        float mn_hi = fmaxf(m_hi, mx_hi);
        float al_lo = __expf(m_lo - mn_lo);
        float al_hi = __expf(m_hi - mn_hi);
        m_lo = mn_lo; m_hi = mn_hi;

        float sum_lo = 0.0f, sum_hi = 0.0f;
#pragma unroll
        for (int j = 0; j < 8; j++) {
            float p0 = __expf(s[j][0] - mn_lo);
            float p1 = __expf(s[j][1] - mn_lo);
            float p2 = __expf(s[j][2] - mn_hi);
            float p3 = __expf(s[j][3] - mn_hi);
            sum_lo += p0 + p1;
            sum_hi += p2 + p3;
            s[j][0] = __uint_as_float(f2tf(p0));
            s[j][1] = __uint_as_float(f2tf(p1));
            s[j][2] = __uint_as_float(f2tf(p2));
            s[j][3] = __uint_as_float(f2tf(p3));
        }
        sum_lo += __shfl_xor_sync(FULL, sum_lo, 1);
        sum_lo += __shfl_xor_sync(FULL, sum_lo, 2);
        sum_hi += __shfl_xor_sync(FULL, sum_hi, 1);
        sum_hi += __shfl_xor_sync(FULL, sum_hi, 2);
        l_lo = l_lo * al_lo + sum_lo;
        l_hi = l_hi * al_hi + sum_hi;

#pragma unroll
        for (int j = 0; j < 8; j++) {
            o[j][0] *= al_lo; o[j][1] *= al_lo;
            o[j][2] *= al_hi; o[j][3] *= al_hi;
        }

#pragma unroll
        for (int kc = 0; kc < 8; kc++) {
            float v00 = __shfl_sync(FULL, s[kc][0], src0);
            float v01 = __shfl_sync(FULL, s[kc][1], src0);
            float v20 = __shfl_sync(FULL, s[kc][2], src0);
            float v21 = __shfl_sync(FULL, s[kc][3], src0);
            float w00 = __shfl_sync(FULL, s[kc][0], src1);
            float w01 = __shfl_sync(FULL, s[kc][1], src1);
            float w20 = __shfl_sync(FULL, s[kc][2], src1);
            float w21 = __shfl_sync(FULL, s[kc][3], src1);
            unsigned pa[4];
            pa[0] = __float_as_uint((tig & 1) ? v01 : v00);
            pa[1] = __float_as_uint((tig & 1) ? v21 : v20);
            pa[2] = __float_as_uint((tig & 1) ? w01 : w00);
            pa[3] = __float_as_uint((tig & 1) ? w21 : w20);

            int r0 = (kc * 8 + tig) * AST;
            int r1 = (kc * 8 + tig + 4) * AST;
#pragma unroll
            for (int jn = 0; jn < 8; jn++) {
                unsigned b0 = __float_as_uint(Vs[r0 + jn * 8 + g]);
                unsigned b1 = __float_as_uint(Vs[r1 + jn * 8 + g]);
                mma_tf32(o[jn], pa, b0, b1);
            }
        }
        __syncthreads();
    }

    float inv_lo = 1.0f / l_lo;
    float inv_hi = 1.0f / l_hi;
    int b = bh / H_, h = bh % H_;
    float* orow_lo = Ob + ((size_t)(b * S_ + qrow0 + g)) * D_ + h * HD_;
    float* orow_hi = Ob + ((size_t)(b * S_ + qrow0 + g + 8)) * D_ + h * HD_;
#pragma unroll
    for (int jn = 0; jn < 8; jn++) {
        float2 wlo = { o[jn][0] * inv_lo, o[jn][1] * inv_lo };
        float2 whi = { o[jn][2] * inv_hi, o[jn][3] * inv_hi };
        *(float2*)(orow_lo + jn * 8 + 2 * tig) = wlo;
        *(float2*)(orow_hi + jn * 8 + 2 * tig) = whi;
    }
}

// ---------------------------------------------------------------------------
// Launch
// ---------------------------------------------------------------------------
extern "C" void kernel_launch(void* const* d_in, const int* in_sizes, int n_in,
                              void* d_out, int out_size)
{
    (void)in_sizes; (void)n_in; (void)out_size;
    const float* x  = (const float*)d_in[0];
    const float* Wq = (const float*)d_in[1];
    const float* bq = (const float*)d_in[2];
    const float* Wk = (const float*)d_in[3];
    const float* bk = (const float*)d_in[4];
    const float* Wv = (const float*)d_in[5];
    const float* bv = (const float*)d_in[6];
    const float* Wo = (const float*)d_in[7];
    const float* bo = (const float*)d_in[8];
    float* out = (float*)d_out;

    void *pq, *pk, *pv, *patt;
    cudaGetSymbolAddress(&pq, g_q);
    cudaGetSymbolAddress(&pk, g_k);
    cudaGetSymbolAddress(&pv, g_v);
    cudaGetSymbolAddress(&patt, g_att);
    float* qb = (float*)pq;
    float* kb = (float*)pk;
    float* vb = (float*)pv;
    float* ab = (float*)patt;

    const int ATT_SMEM = 4 * ATILE * (int)sizeof(float);   // 69632 B
    cudaFuncSetAttribute(attn_kernel, cudaFuncAttributeMaxDynamicSharedMemorySize, ATT_SMEM);

    dim3 ggrid(D_ / GBN, M_TOT / GBM);   // (8, 32)
    gemm_tf32_kernel<<<ggrid, 256>>>(x, Wq, bq, qb, M_TOT, D_, D_, 1, 0.125f);
    gemm_tf32_kernel<<<ggrid, 256>>>(x, Wk, bk, kb, M_TOT, D_, D_, 1, 1.0f);
    gemm_tf32_kernel<<<ggrid, 256>>>(x, Wv, bv, vb, M_TOT, D_, D_, 1, 1.0f);

    dim3 agrid(S_ / AQ, B_ * H_);        // (32, 32)
    attn_kernel<<<agrid, 128, ATT_SMEM>>>(qb, kb, vb, ab);

    gemm_tf32_kernel<<<ggrid, 256>>>(ab, Wo, bo, out, M_TOT, D_, D_, 0, 1.0f);
}

// round 9
// speedup vs baseline: 1.0962x; 1.0214x over previous
#include <cuda_runtime.h>

// Problem constants (fixed shapes)
#define B_   2
#define S_   2048
#define D_   1024
#define H_   16
#define HD_  64
#define M_TOT (B_ * S_)   // 4096

// ---------------------------------------------------------------------------
// Scratch buffers. g_q/g_k/g_v/g_att/g_xt/g_wt hold tf32-ROUNDED bit patterns
// (Q pre-scaled by 1/sqrt(HD)).
// ---------------------------------------------------------------------------
__device__ float g_q[B_ * H_ * S_ * HD_];    // [B,H,S,HD] tf32 bits
__device__ float g_k[B_ * H_ * S_ * HD_];
__device__ float g_v[B_ * H_ * S_ * HD_];
__device__ float g_att[B_ * S_ * D_];        // [B,S,D] tf32 bits
__device__ float g_xt[M_TOT * D_];           // x converted to tf32 bits
__device__ float g_wt[4 * D_ * D_];          // Wq,Wk,Wv,Wo tf32 bits

// ---------------------------------------------------------------------------
// Helpers
// ---------------------------------------------------------------------------
__device__ __forceinline__ unsigned f2tf(float x) {
    unsigned u;
    asm("cvt.rna.tf32.f32 %0, %1;" : "=r"(u) : "f"(x));
    return u;
}

__device__ __forceinline__ void mma_tf32(float* d, const unsigned* a,
                                         unsigned b0, unsigned b1) {
    asm volatile(
        "mma.sync.aligned.m16n8k8.row.col.f32.tf32.tf32.f32 "
        "{%0,%1,%2,%3}, {%4,%5,%6,%7}, {%8,%9}, {%0,%1,%2,%3};"
        : "+f"(d[0]), "+f"(d[1]), "+f"(d[2]), "+f"(d[3])
        : "r"(a[0]), "r"(a[1]), "r"(a[2]), "r"(a[3]), "r"(b0), "r"(b1));
}

__device__ __forceinline__ void cp_async16(void* smem_dst, const void* gmem_src) {
    unsigned saddr = (unsigned)__cvta_generic_to_shared(smem_dst);
    asm volatile("cp.async.cg.shared.global [%0], [%1], 16;"
                 :: "r"(saddr), "l"(gmem_src));
}

// ---------------------------------------------------------------------------
// Prep: convert x and the 4 weight matrices to tf32 bit patterns (one pass).
// ---------------------------------------------------------------------------
#define XN4 (M_TOT * D_ / 4)       // 1048576 float4
#define WN4 (D_ * D_ / 4)          // 262144 float4 each

__global__ void __launch_bounds__(256) cvt_prep_kernel(
    const float* __restrict__ x,
    const float* __restrict__ wq, const float* __restrict__ wk,
    const float* __restrict__ wv, const float* __restrict__ wo,
    float* __restrict__ xt, float* __restrict__ wt)
{
    int i = blockIdx.x * 256 + threadIdx.x;
    const float4* s;
    uint4* d;
    if (i < XN4) {
        s = (const float4*)x + i;
        d = (uint4*)xt + i;
    } else {
        int j = i - XN4;
        int w = j >> 18;            // /262144
        int off = j & (WN4 - 1);
        const float* ws = (w == 0) ? wq : (w == 1) ? wk : (w == 2) ? wv : wo;
        s = (const float4*)ws + off;
        d = (uint4*)(wt + (size_t)w * D_ * D_) + off;
    }
    float4 v = *s;
    uint4 u = { f2tf(v.x), f2tf(v.y), f2tf(v.z), f2tf(v.w) };
    *d = u;
}

// ---------------------------------------------------------------------------
// GEMM v3: inputs are tf32 bits; 3-stage cp.async pipeline, ZERO cvt in
// mainloop, ONE barrier per K-tile. CTA tile 128x128x32, 8 warps.
// ---------------------------------------------------------------------------
#define GBM 128
#define GBN 128
#define GBK 32
#define GASTR 36
#define GBSTR 136
#define ASZ (GBM * GASTR)          // 4608 floats
#define BSZ (GBK * GBSTR)          // 4352 floats
#define GSTAGE (ASZ + BSZ)         // 8960 floats
#define GSM_BYTES (3 * GSTAGE * 4) // 107520 B

extern __shared__ float gsm[];

#define GEMM_ISSUE(t)                                                     \
    do {                                                                  \
        float* Ad = gsm + ((t) % 3) * GSTAGE + arow * GASTR + acol;       \
        float* Bd = gsm + ((t) % 3) * GSTAGE + ASZ + brow * GBSTR + bcol; \
        const float* Asrc = Ag + (t) * GBK;                               \
        const float* Bsrc = Bg + (size_t)(t) * GBK * N;                   \
        _Pragma("unroll")                                                 \
        for (int p = 0; p < 4; p++) {                                     \
            cp_async16(Ad + p * 4, Asrc + p * 4);                         \
            cp_async16(Bd + p * 4, Bsrc + p * 4);                         \
        }                                                                 \
        asm volatile("cp.async.commit_group;");                           \
    } while (0)

__global__ void __launch_bounds__(256, 2) gemm_tf32_kernel(
    const float* __restrict__ A, const float* __restrict__ W,
    const float* __restrict__ bias, float* __restrict__ out,
    int M, int N, int K, int qkv_mode, float oscale)
{
    const int tid  = threadIdx.x;
    const int warp = tid >> 5;
    const int lane = tid & 31;
    const int g    = lane >> 2;
    const int tig  = lane & 3;
    const int wm   = (warp >> 2) * 64;
    const int wn   = (warp & 3) * 32;
    const int bm   = blockIdx.y * GBM;
    const int bn   = blockIdx.x * GBN;

    const int arow = tid >> 1;          // 0..127
    const int acol = (tid & 1) * 16;    // 0,16
    const int brow = tid >> 3;          // 0..31
    const int bcol = (tid & 7) * 16;    // 0..112

    const float* Ag = A + (size_t)(bm + arow) * K + acol;
    const float* Bg = W + (size_t)brow * N + bn + bcol;

    float acc[16][4];
#pragma unroll
    for (int f = 0; f < 16; f++)
#pragma unroll
        for (int e = 0; e < 4; e++) acc[f][e] = 0.0f;

    const int NT = K / GBK;             // 32
    GEMM_ISSUE(0);
    GEMM_ISSUE(1);

    for (int t = 0; t < NT; t++) {
        if (t < NT - 1) {
            asm volatile("cp.async.wait_group 1;");
        } else {
            asm volatile("cp.async.wait_group 0;");
        }
        __syncthreads();

        if (t + 2 < NT) GEMM_ISSUE(t + 2);

        const float* Ac = gsm + (t % 3) * GSTAGE;
        const float* Bc = Ac + ASZ;

#pragma unroll
        for (int kk = 0; kk < GBK; kk += 8) {
            unsigned af[4][4];
#pragma unroll
            for (int i = 0; i < 4; i++) {
                const float* base = Ac + (wm + i * 16 + g) * GASTR + kk + tig;
                af[i][0] = __float_as_uint(base[0]);
                af[i][1] = __float_as_uint(base[8 * GASTR]);
                af[i][2] = __float_as_uint(base[4]);
                af[i][3] = __float_as_uint(base[8 * GASTR + 4]);
            }
            unsigned bf[4][2];
#pragma unroll
            for (int j = 0; j < 4; j++) {
                bf[j][0] = __float_as_uint(Bc[(kk + tig) * GBSTR + wn + j * 8 + g]);
                bf[j][1] = __float_as_uint(Bc[(kk + tig + 4) * GBSTR + wn + j * 8 + g]);
            }
#pragma unroll
            for (int i = 0; i < 4; i++)
#pragma unroll
                for (int j = 0; j < 4; j++)
                    mma_tf32(acc[i * 4 + j], af[i], bf[j][0], bf[j][1]);
        }
        // no trailing barrier: next iteration's top barrier protects reuse
    }

    // ---- Register epilogue ----
#pragma unroll
    for (int i = 0; i < 4; i++) {
#pragma unroll
        for (int j = 0; j < 4; j++) {
            const float* d = acc[i * 4 + j];
            int col = bn + wn + j * 8 + 2 * tig;
            float2 b2 = *(const float2*)(bias + col);
            int row_lo = bm + wm + i * 16 + g;
            float2 vlo = { d[0] + b2.x, d[1] + b2.y };
            float2 vhi = { d[2] + b2.x, d[3] + b2.y };
            if (qkv_mode) {
                uint2 tlo = { f2tf(vlo.x * oscale), f2tf(vlo.y * oscale) };
                uint2 thi = { f2tf(vhi.x * oscale), f2tf(vhi.y * oscale) };
                int h = col / HD_, dd = col % HD_;
                int b0i = row_lo / S_, s0 = row_lo % S_;
                *(uint2*)(out + ((size_t)((b0i * H_ + h) * S_ + s0)) * HD_ + dd) = tlo;
                int row_hi = row_lo + 8;
                int b1i = row_hi / S_, s1 = row_hi % S_;
                *(uint2*)(out + ((size_t)((b1i * H_ + h) * S_ + s1)) * HD_ + dd) = thi;
            } else {
                *(float2*)(out + (size_t)row_lo * N + col) = vlo;
                *(float2*)(out + (size_t)(row_lo + 8) * N + col) = vhi;
            }
        }
    }
}

// ---------------------------------------------------------------------------
// Flash attention v7: register S/P/O; K double-buffered via cp.async,
// V SINGLE-buffered (smem 52 KB -> 4 CTAs/SM). Writes tf32 bits to g_att.
// ---------------------------------------------------------------------------
#define AQ  64
#define AKV 64
#define AST 68
#define ATILE (AKV * AST)
#define ATT_SMEM (3 * ATILE * 4)   // 52224 B

extern __shared__ float attn_sm[];

__global__ void __launch_bounds__(128, 4) attn_kernel(
    const float* __restrict__ Qb, const float* __restrict__ Kb,
    const float* __restrict__ Vb, float* __restrict__ Ob)
{
    float* Ks0 = attn_sm;
    float* Ks1 = attn_sm + ATILE;
    float* Vs  = attn_sm + 2 * ATILE;

    const int bh   = blockIdx.y;
    const int qt   = blockIdx.x;
    const int tid  = threadIdx.x;
    const int warp = tid >> 5;
    const int lane = tid & 31;
    const int g    = lane >> 2;
    const int tig  = lane & 3;

    const int lr = tid >> 4;
    const int lc = (tid & 15) * 4;

    const float* Kbase = Kb + (size_t)bh * S_ * HD_;
    const float* Vbase = Vb + (size_t)bh * S_ * HD_;

    // Prologue: K0 + V0 as one group
    {
#pragma unroll
        for (int i = 0; i < 8; i++) {
            int r = i * 8 + lr;
            cp_async16(Ks0 + r * AST + lc, Kbase + (size_t)r * HD_ + lc);
            cp_async16(Vs + r * AST + lc, Vbase + (size_t)r * HD_ + lc);
        }
        asm volatile("cp.async.commit_group;");
    }

    // Q fragments: raw tf32 bits (pre-scaled by 0.125)
    const int qrow0 = qt * AQ + warp * 16;
    const float* Qp = Qb + ((size_t)bh * S_ + qrow0) * HD_;
    unsigned qa[8][4];
#pragma unroll
    for (int kc = 0; kc < 8; kc++) {
        int c0 = kc * 8 + tig;
        qa[kc][0] = __float_as_uint(Qp[(size_t)g * HD_ + c0]);
        qa[kc][1] = __float_as_uint(Qp[(size_t)(g + 8) * HD_ + c0]);
        qa[kc][2] = __float_as_uint(Qp[(size_t)g * HD_ + c0 + 4]);
        qa[kc][3] = __float_as_uint(Qp[(size_t)(g + 8) * HD_ + c0 + 4]);
    }

    float o[8][4];
#pragma unroll
    for (int j = 0; j < 8; j++)
#pragma unroll
        for (int e = 0; e < 4; e++) o[j][e] = 0.0f;
    float m_lo = -1e30f, m_hi = -1e30f;
    float l_lo = 0.0f,   l_hi = 0.0f;

    const unsigned FULL = 0xffffffffu;
    const int src0 = (lane & ~3) | (tig >> 1);
    const int src1 = src0 + 2;

    const int NT = S_ / AKV;
    for (int kt = 0; kt < NT; kt++) {
        // Issue K(t+1) into the other K buffer
        if (kt + 1 < NT) {
            float* Kd = ((kt + 1) & 1) ? Ks1 : Ks0;
            const float* Kp = Kbase + (size_t)(kt + 1) * AKV * HD_;
#pragma unroll
            for (int i = 0; i < 8; i++) {
                int r = i * 8 + lr;
                cp_async16(Kd + r * AST + lc, Kp + (size_t)r * HD_ + lc);
            }
            asm volatile("cp.async.commit_group;");
            asm volatile("cp.async.wait_group 1;");   // K(t) and V(t) done
        } else {
            asm volatile("cp.async.wait_group 0;");
        }
        __syncthreads();

        const float* Ks = (kt & 1) ? Ks1 : Ks0;

        // ---- S = Qs @ K^T ----
        float s[8][4];
#pragma unroll
        for (int j = 0; j < 8; j++)
#pragma unroll
            for (int e = 0; e < 4; e++) s[j][e] = 0.0f;

#pragma unroll
        for (int kc = 0; kc < 8; kc++) {
            int c0 = kc * 8 + tig;
#pragma unroll
            for (int j = 0; j < 8; j++) {
                unsigned b0 = __float_as_uint(Ks[(j * 8 + g) * AST + c0]);
                unsigned b1 = __float_as_uint(Ks[(j * 8 + g) * AST + c0 + 4]);
                mma_tf32(s[j], qa[kc], b0, b1);
            }
        }

        // ---- Online softmax ----
        float mx_lo = -1e30f, mx_hi = -1e30f;
#pragma unroll
        for (int j = 0; j < 8; j++) {
            mx_lo = fmaxf(mx_lo, fmaxf(s[j][0], s[j][1]));
            mx_hi = fmaxf(mx_hi, fmaxf(s[j][2], s[j][3]));
        }
        mx_lo = fmaxf(mx_lo, __shfl_xor_sync(FULL, mx_lo, 1));
        mx_lo = fmaxf(mx_lo, __shfl_xor_sync(FULL, mx_lo, 2));
        mx_hi = fmaxf(mx_hi, __shfl_xor_sync(FULL, mx_hi, 1));
        mx_hi = fmaxf(mx_hi, __shfl_xor_sync(FULL, mx_hi, 2));

        float mn_lo = fmaxf(m_lo, mx_lo);
        float mn_hi = fmaxf(m_hi, mx_hi);
        float al_lo = __expf(m_lo - mn_lo);
        float al_hi = __expf(m_hi - mn_hi);
        m_lo = mn_lo; m_hi = mn_hi;

        float sum_lo = 0.0f, sum_hi = 0.0f;
#pragma unroll
        for (int j = 0; j < 8; j++) {
            float p0 = __expf(s[j][0] - mn_lo);
            float p1 = __expf(s[j][1] - mn_lo);
            float p2 = __expf(s[j][2] - mn_hi);
            float p3 = __expf(s[j][3] - mn_hi);
            sum_lo += p0 + p1;
            sum_hi += p2 + p3;
            s[j][0] = __uint_as_float(f2tf(p0));
            s[j][1] = __uint_as_float(f2tf(p1));
            s[j][2] = __uint_as_float(f2tf(p2));
            s[j][3] = __uint_as_float(f2tf(p3));
        }
        sum_lo += __shfl_xor_sync(FULL, sum_lo, 1);
        sum_lo += __shfl_xor_sync(FULL, sum_lo, 2);
        sum_hi += __shfl_xor_sync(FULL, sum_hi, 1);
        sum_hi += __shfl_xor_sync(FULL, sum_hi, 2);
        l_lo = l_lo * al_lo + sum_lo;
        l_hi = l_hi * al_hi + sum_hi;

#pragma unroll
        for (int j = 0; j < 8; j++) {
            o[j][0] *= al_lo; o[j][1] *= al_lo;
            o[j][2] *= al_hi; o[j][3] *= al_hi;
        }

        // ---- O += P @ V ----
#pragma unroll
        for (int kc = 0; kc < 8; kc++) {
            float v00 = __shfl_sync(FULL, s[kc][0], src0);
            float v01 = __shfl_sync(FULL, s[kc][1], src0);
            float v20 = __shfl_sync(FULL, s[kc][2], src0);
            float v21 = __shfl_sync(FULL, s[kc][3], src0);
            float w00 = __shfl_sync(FULL, s[kc][0], src1);
            float w01 = __shfl_sync(FULL, s[kc][1], src1);
            float w20 = __shfl_sync(FULL, s[kc][2], src1);
            float w21 = __shfl_sync(FULL, s[kc][3], src1);
            unsigned pa[4];
            pa[0] = __float_as_uint((tig & 1) ? v01 : v00);
            pa[1] = __float_as_uint((tig & 1) ? v21 : v20);
            pa[2] = __float_as_uint((tig & 1) ? w01 : w00);
            pa[3] = __float_as_uint((tig & 1) ? w21 : w20);

            int r0 = (kc * 8 + tig) * AST;
            int r1 = (kc * 8 + tig + 4) * AST;
#pragma unroll
            for (int jn = 0; jn < 8; jn++) {
                unsigned b0 = __float_as_uint(Vs[r0 + jn * 8 + g]);
                unsigned b1 = __float_as_uint(Vs[r1 + jn * 8 + g]);
                mma_tf32(o[jn], pa, b0, b1);
            }
        }
        __syncthreads();   // all warps done reading Vs

        // Issue V(t+1) into the single V buffer
        if (kt + 1 < NT) {
            const float* Vp = Vbase + (size_t)(kt + 1) * AKV * HD_;
#pragma unroll
            for (int i = 0; i < 8; i++) {
                int r = i * 8 + lr;
                cp_async16(Vs + r * AST + lc, Vp + (size_t)r * HD_ + lc);
            }
            asm volatile("cp.async.commit_group;");
        }
    }

    // ---- Normalize, write tf32 bits to [B,S,D] ----
    float inv_lo = 1.0f / l_lo;
    float inv_hi = 1.0f / l_hi;
    int b = bh / H_, h = bh % H_;
    float* orow_lo = Ob + ((size_t)(b * S_ + qrow0 + g)) * D_ + h * HD_;
    float* orow_hi = Ob + ((size_t)(b * S_ + qrow0 + g + 8)) * D_ + h * HD_;
#pragma unroll
    for (int jn = 0; jn < 8; jn++) {
        uint2 wlo = { f2tf(o[jn][0] * inv_lo), f2tf(o[jn][1] * inv_lo) };
        uint2 whi = { f2tf(o[jn][2] * inv_hi), f2tf(o[jn][3] * inv_hi) };
        *(uint2*)(orow_lo + jn * 8 + 2 * tig) = wlo;
        *(uint2*)(orow_hi + jn * 8 + 2 * tig) = whi;
    }
}

// ---------------------------------------------------------------------------
// Launch
// ---------------------------------------------------------------------------
extern "C" void kernel_launch(void* const* d_in, const int* in_sizes, int n_in,
                              void* d_out, int out_size)
{
    (void)in_sizes; (void)n_in; (void)out_size;
    const float* x  = (const float*)d_in[0];
    const float* Wq = (const float*)d_in[1];
    const float* bq = (const float*)d_in[2];
    const float* Wk = (const float*)d_in[3];
    const float* bk = (const float*)d_in[4];
    const float* Wv = (const float*)d_in[5];
    const float* bv = (const float*)d_in[6];
    const float* Wo = (const float*)d_in[7];
    const float* bo = (const float*)d_in[8];
    float* out = (float*)d_out;

    void *pq, *pk, *pv, *patt, *pxt, *pwt;
    cudaGetSymbolAddress(&pq, g_q);
    cudaGetSymbolAddress(&pk, g_k);
    cudaGetSymbolAddress(&pv, g_v);
    cudaGetSymbolAddress(&patt, g_att);
    cudaGetSymbolAddress(&pxt, g_xt);
    cudaGetSymbolAddress(&pwt, g_wt);
    float* qb = (float*)pq;
    float* kb = (float*)pk;
    float* vb = (float*)pv;
    float* ab = (float*)patt;
    float* xt = (float*)pxt;
    float* wt = (float*)pwt;

    cudaFuncSetAttribute(gemm_tf32_kernel,
                         cudaFuncAttributeMaxDynamicSharedMemorySize, GSM_BYTES);
    cudaFuncSetAttribute(attn_kernel,
                         cudaFuncAttributeMaxDynamicSharedMemorySize, ATT_SMEM);

    // 1) Convert x + weights to tf32 bits
    int nthreads = XN4 + 4 * WN4;                 // 2097152
    cvt_prep_kernel<<<nthreads / 256, 256>>>(x, Wq, Wk, Wv, Wo, xt, wt);

    // 2) QKV projections (tf32-bit inputs, zero-cvt mainloop)
    dim3 ggrid(D_ / GBN, M_TOT / GBM);            // (8, 32)
    gemm_tf32_kernel<<<ggrid, 256, GSM_BYTES>>>(xt, wt + 0 * D_ * D_, bq, qb,
                                                M_TOT, D_, D_, 1, 0.125f);
    gemm_tf32_kernel<<<ggrid, 256, GSM_BYTES>>>(xt, wt + 1 * D_ * D_, bk, kb,
                                                M_TOT, D_, D_, 1, 1.0f);
    gemm_tf32_kernel<<<ggrid, 256, GSM_BYTES>>>(xt, wt + 2 * D_ * D_, bv, vb,
                                                M_TOT, D_, D_, 1, 1.0f);

    // 3) Attention
    dim3 agrid(S_ / AQ, B_ * H_);                 // (32, 32)
    attn_kernel<<<agrid, 128, ATT_SMEM>>>(qb, kb, vb, ab);

    // 4) Output projection (g_att already tf32 bits)
    gemm_tf32_kernel<<<ggrid, 256, GSM_BYTES>>>(ab, wt + 3 * D_ * D_, bo, out,
                                                M_TOT, D_, D_, 0, 1.0f);
}

// round 11
// speedup vs baseline: 2.5246x; 2.3031x over previous
#include <cuda_runtime.h>
#include <cuda_fp16.h>
#include <cstdint>

// Problem constants (fixed shapes)
#define B_   2
#define S_   2048
#define D_   1024
#define H_   16
#define HD_  64
#define M_TOT (B_ * S_)   // 4096

// ---------------------------------------------------------------------------
// Scratch buffers (fp16; Q pre-scaled by 1/sqrt(HD); V stored TRANSPOSED)
// ---------------------------------------------------------------------------
__device__ __half g_q[B_ * H_ * S_ * HD_];    // [B,H,S,HD]
__device__ __half g_k[B_ * H_ * S_ * HD_];    // [B,H,S,HD]
__device__ __half g_v[B_ * H_ * S_ * HD_];    // [B,H,HD,S]  (transposed!)
__device__ __half g_att[B_ * S_ * D_];        // [B,S,D]
__device__ __half g_xt[M_TOT * D_];           // x in fp16 [M,K]
__device__ __half g_wt[4 * D_ * D_];          // W^T fp16 [N,K] x4

// ---------------------------------------------------------------------------
// Helpers
// ---------------------------------------------------------------------------
__device__ __forceinline__ void mma_f16(float* d, const unsigned* a,
                                        unsigned b0, unsigned b1) {
    asm volatile(
        "mma.sync.aligned.m16n8k16.row.col.f32.f16.f16.f32 "
        "{%0,%1,%2,%3}, {%4,%5,%6,%7}, {%8,%9}, {%0,%1,%2,%3};"
        : "+f"(d[0]), "+f"(d[1]), "+f"(d[2]), "+f"(d[3])
        : "r"(a[0]), "r"(a[1]), "r"(a[2]), "r"(a[3]), "r"(b0), "r"(b1));
}

__device__ __forceinline__ void cp_async16(void* smem_dst, const void* gmem_src) {
    unsigned saddr = (unsigned)__cvta_generic_to_shared(smem_dst);
    asm volatile("cp.async.cg.shared.global [%0], [%1], 16;"
                 :: "r"(saddr), "l"(gmem_src));
}

__device__ __forceinline__ unsigned pack_h2(float lo, float hi) {
    __half2 h = __floats2half2_rn(lo, hi);
    return *reinterpret_cast<unsigned*>(&h);
}

// ---------------------------------------------------------------------------
// Prep: x -> fp16; W -> W^T fp16 [N,K]
// ---------------------------------------------------------------------------
__global__ void __launch_bounds__(256) xcvt_kernel(const float* __restrict__ x,
                                                   __half* __restrict__ xt) {
    int i = blockIdx.x * 256 + threadIdx.x;
    float4 v = ((const float4*)x)[i];
    __half2 h0 = __floats2half2_rn(v.x, v.y);
    __half2 h1 = __floats2half2_rn(v.z, v.w);
    ((__half2*)xt)[2 * i]     = h0;
    ((__half2*)xt)[2 * i + 1] = h1;
}

__global__ void wtrans_kernel(const float* __restrict__ wq,
                              const float* __restrict__ wk,
                              const float* __restrict__ wv,
                              const float* __restrict__ wo,
                              __half* __restrict__ wt) {
    __shared__ float tile[32][33];
    int w = blockIdx.z;
    const float* src = (w == 0) ? wq : (w == 1) ? wk : (w == 2) ? wv : wo;
    __half* dst = wt + (size_t)w * D_ * D_;
    int k0 = blockIdx.y * 32, n0 = blockIdx.x * 32;
    int tx = threadIdx.x, ty = threadIdx.y;
#pragma unroll
    for (int j = 0; j < 32; j += 8)
        tile[ty + j][tx] = src[(size_t)(k0 + ty + j) * D_ + n0 + tx];
    __syncthreads();
#pragma unroll
    for (int j = 0; j < 32; j += 8)
        dst[(size_t)(n0 + ty + j) * D_ + k0 + tx] = __float2half(tile[tx][ty + j]);
}

// ---------------------------------------------------------------------------
// FP16 GEMM: out = A[M,K] @ Wt[N,K]^T + bias. CTA 128x128, K-tile 64 halfs,
// 3-stage cp.async ring, warp tile 64x32, mma.m16n8k16.
// mode 0: fp32 [M,N]; mode 1: fp16 scatter [B,H,S,HD]; mode 2: fp16 [B,H,HD,S]
// ---------------------------------------------------------------------------
#define GSTR 72                      // halfs per smem row
#define ABYTES (128 * GSTR * 2)      // 18432 B per operand stage
#define STAGEB (2 * ABYTES)          // 36864 B
#define GSMB (3 * STAGEB)            // 110592 B

extern __shared__ char tsm[];

#define GEMM_ISSUE(t)                                                        \
    do {                                                                     \
        char* sbase = tsm + ((t) % 3) * STAGEB;                              \
        _Pragma("unroll")                                                    \
        for (int ii = 0; ii < 4; ii++) {                                     \
            int idx = ii * 256 + tid;                                        \
            int r = idx >> 3, seg = idx & 7;                                 \
            cp_async16(sbase + r * (GSTR * 2) + seg * 16,                    \
                       Ag + (size_t)r * D_ + (t) * 64 + seg * 8);            \
            cp_async16(sbase + ABYTES + r * (GSTR * 2) + seg * 16,           \
                       Bg + (size_t)r * D_ + (t) * 64 + seg * 8);            \
        }                                                                    \
        asm volatile("cp.async.commit_group;");                              \
    } while (0)

__global__ void __launch_bounds__(256, 2) gemm_f16_kernel(
    const __half* __restrict__ A, const __half* __restrict__ Wt,
    const float* __restrict__ bias, void* __restrict__ out,
    int mode, float oscale)
{
    const int tid  = threadIdx.x;
    const int warp = tid >> 5;
    const int lane = tid & 31;
    const int g    = lane >> 2;
    const int tig  = lane & 3;
    const int wm   = (warp >> 2) * 64;
    const int wn   = (warp & 3) * 32;
    const int bm   = blockIdx.y * 128;
    const int bn   = blockIdx.x * 128;

    const __half* Ag = A + (size_t)bm * D_;
    const __half* Bg = Wt + (size_t)bn * D_;

    float acc[16][4];
#pragma unroll
    for (int f = 0; f < 16; f++)
#pragma unroll
        for (int e = 0; e < 4; e++) acc[f][e] = 0.0f;

    const int NT = D_ / 64;          // 16
    GEMM_ISSUE(0);
    GEMM_ISSUE(1);

    for (int t = 0; t < NT; t++) {
        if (t < NT - 1) asm volatile("cp.async.wait_group 1;");
        else            asm volatile("cp.async.wait_group 0;");
        __syncthreads();

        if (t + 2 < NT) GEMM_ISSUE(t + 2);

        const __half* As_h = (const __half*)(tsm + (t % 3) * STAGEB);
        const __half* Bs_h = (const __half*)(tsm + (t % 3) * STAGEB + ABYTES);

#pragma unroll
        for (int ks = 0; ks < 4; ks++) {
            int kh = ks * 16;
            unsigned af[4][4];
#pragma unroll
            for (int i = 0; i < 4; i++) {
                int rlo = wm + i * 16 + g;
                af[i][0] = *(const unsigned*)(As_h + rlo * GSTR + kh + 2 * tig);
                af[i][1] = *(const unsigned*)(As_h + (rlo + 8) * GSTR + kh + 2 * tig);
                af[i][2] = *(const unsigned*)(As_h + rlo * GSTR + kh + 8 + 2 * tig);
                af[i][3] = *(const unsigned*)(As_h + (rlo + 8) * GSTR + kh + 8 + 2 * tig);
            }
            unsigned bf[4][2];
#pragma unroll
            for (int j = 0; j < 4; j++) {
                int nr = wn + j * 8 + g;
                bf[j][0] = *(const unsigned*)(Bs_h + nr * GSTR + kh + 2 * tig);
                bf[j][1] = *(const unsigned*)(Bs_h + nr * GSTR + kh + 8 + 2 * tig);
            }
#pragma unroll
            for (int i = 0; i < 4; i++)
#pragma unroll
                for (int j = 0; j < 4; j++)
                    mma_f16(acc[i * 4 + j], af[i], bf[j][0], bf[j][1]);
        }
    }

    // ---- Epilogue ----
#pragma unroll
    for (int i = 0; i < 4; i++) {
#pragma unroll
        for (int j = 0; j < 4; j++) {
            const float* d = acc[i * 4 + j];
            int col = bn + wn + j * 8 + 2 * tig;
            float2 b2 = *(const float2*)(bias + col);
            int row_lo = bm + wm + i * 16 + g;
            int row_hi = row_lo + 8;
            float2 vlo = { (d[0] + b2.x) * oscale, (d[1] + b2.y) * oscale };
            float2 vhi = { (d[2] + b2.x) * oscale, (d[3] + b2.y) * oscale };
            if (mode == 0) {
                float* of = (float*)out;
                *(float2*)(of + (size_t)row_lo * D_ + col) = vlo;
                *(float2*)(of + (size_t)row_hi * D_ + col) = vhi;
            } else if (mode == 1) {
                __half* oh = (__half*)out;
                int h = col / HD_, dd = col % HD_;
                int b0i = row_lo / S_, s0 = row_lo % S_;
                int b1i = row_hi / S_, s1 = row_hi % S_;
                *(__half2*)(oh + ((size_t)((b0i * H_ + h) * S_ + s0)) * HD_ + dd)
                    = __floats2half2_rn(vlo.x, vlo.y);
                *(__half2*)(oh + ((size_t)((b1i * H_ + h) * S_ + s1)) * HD_ + dd)
                    = __floats2half2_rn(vhi.x, vhi.y);
            } else {
                // mode 2: V transposed [B,H,HD,S]
                __half* oh = (__half*)out;
                int h = col / HD_, dd = col % HD_;
                int b0i = row_lo / S_, s0 = row_lo % S_;
                int b1i = row_hi / S_, s1 = row_hi % S_;
                oh[((size_t)((b0i * H_ + h) * HD_ + dd)) * S_ + s0]     = __float2half(vlo.x);
                oh[((size_t)((b0i * H_ + h) * HD_ + dd + 1)) * S_ + s0] = __float2half(vlo.y);
                oh[((size_t)((b1i * H_ + h) * HD_ + dd)) * S_ + s1]     = __float2half(vhi.x);
                oh[((size_t)((b1i * H_ + h) * HD_ + dd + 1)) * S_ + s1] = __float2half(vhi.y);
            }
        }
    }
}

// ---------------------------------------------------------------------------
// Flash attention fp16: register S/P/O, mma.m16n8k16, zero shuffles (fp16
// A-frag layout == C layout pairing). K double-buffered, Vt single-buffered.
// ---------------------------------------------------------------------------
#define AKV 64
#define AQ  64
#define KSTR 72
#define KTILE_B (64 * KSTR * 2)      // 9216 B

__global__ void __launch_bounds__(128, 4) attn_kernel(
    const __half* __restrict__ Qb, const __half* __restrict__ Kb,
    const __half* __restrict__ Vtb, __half* __restrict__ Ob)
{
    __shared__ __half Ks0[64 * KSTR];
    __shared__ __half Ks1[64 * KSTR];
    __shared__ __half Vts[64 * KSTR];

    const int bh   = blockIdx.y;
    const int qt   = blockIdx.x;
    const int tid  = threadIdx.x;
    const int warp = tid >> 5;
    const int lane = tid & 31;
    const int g    = lane >> 2;
    const int tig  = lane & 3;

    const __half* Kbase  = Kb + (size_t)bh * S_ * HD_;
    const __half* Vtbase = Vtb + (size_t)bh * HD_ * S_;   // [HD][S]

    // Prologue: K0 + Vt0 (one group)
    {
#pragma unroll
        for (int i = 0; i < 4; i++) {
            int idx = i * 128 + tid;
            int r = idx >> 3, seg = idx & 7;
            cp_async16((char*)Ks0 + r * (KSTR * 2) + seg * 16,
                       Kbase + (size_t)r * HD_ + seg * 8);
            cp_async16((char*)Vts + r * (KSTR * 2) + seg * 16,
                       Vtbase + (size_t)r * S_ + seg * 8);
        }
        asm volatile("cp.async.commit_group;");
    }

    // Q fragments (fp16, pre-scaled): 4 k16-steps x 4 regs
    const int qrow0 = qt * AQ + warp * 16;
    const __half* Qp = Qb + ((size_t)bh * S_ + qrow0) * HD_;
    unsigned qa[4][4];
#pragma unroll
    for (int kc = 0; kc < 4; kc++) {
        int kh = kc * 16;
        qa[kc][0] = *(const unsigned*)(Qp + (size_t)g * HD_ + kh + 2 * tig);
        qa[kc][1] = *(const unsigned*)(Qp + (size_t)(g + 8) * HD_ + kh + 2 * tig);
        qa[kc][2] = *(const unsigned*)(Qp + (size_t)g * HD_ + kh + 8 + 2 * tig);
        qa[kc][3] = *(const unsigned*)(Qp + (size_t)(g + 8) * HD_ + kh + 8 + 2 * tig);
    }

    float o[8][4];
#pragma unroll
    for (int j = 0; j < 8; j++)
#pragma unroll
        for (int e = 0; e < 4; e++) o[j][e] = 0.0f;
    float m_lo = -1e30f, m_hi = -1e30f;
    float l_lo = 0.0f,   l_hi = 0.0f;
    const unsigned FULL = 0xffffffffu;

    const int NT = S_ / AKV;
    for (int kt = 0; kt < NT; kt++) {
        if (kt + 1 < NT) {
            __half* Kd = ((kt + 1) & 1) ? Ks1 : Ks0;
            const __half* Kp = Kbase + (size_t)(kt + 1) * AKV * HD_;
#pragma unroll
            for (int i = 0; i < 4; i++) {
                int idx = i * 128 + tid;
                int r = idx >> 3, seg = idx & 7;
                cp_async16((char*)Kd + r * (KSTR * 2) + seg * 16,
                           Kp + (size_t)r * HD_ + seg * 8);
            }
            asm volatile("cp.async.commit_group;");
            asm volatile("cp.async.wait_group 1;");
        } else {
            asm volatile("cp.async.wait_group 0;");
        }
        __syncthreads();

        const __half* Ks = (kt & 1) ? Ks1 : Ks0;

        // ---- S = Q @ K^T : 8 n-chunks, 4 k16-steps -> 32 MMAs ----
        float s[8][4];
#pragma unroll
        for (int j = 0; j < 8; j++)
#pragma unroll
            for (int e = 0; e < 4; e++) s[j][e] = 0.0f;

#pragma unroll
        for (int kc = 0; kc < 4; kc++) {
            int kh = kc * 16;
#pragma unroll
            for (int j = 0; j < 8; j++) {
                int kr = (j * 8 + g) * KSTR;
                unsigned b0 = *(const unsigned*)(Ks + kr + kh + 2 * tig);
                unsigned b1 = *(const unsigned*)(Ks + kr + kh + 8 + 2 * tig);
                mma_f16(s[j], qa[kc], b0, b1);
            }
        }

        // ---- Online softmax ----
        float mx_lo = -1e30f, mx_hi = -1e30f;
#pragma unroll
        for (int j = 0; j < 8; j++) {
            mx_lo = fmaxf(mx_lo, fmaxf(s[j][0], s[j][1]));
            mx_hi = fmaxf(mx_hi, fmaxf(s[j][2], s[j][3]));
        }
        mx_lo = fmaxf(mx_lo, __shfl_xor_sync(FULL, mx_lo, 1));
        mx_lo = fmaxf(mx_lo, __shfl_xor_sync(FULL, mx_lo, 2));
        mx_hi = fmaxf(mx_hi, __shfl_xor_sync(FULL, mx_hi, 1));
        mx_hi = fmaxf(mx_hi, __shfl_xor_sync(FULL, mx_hi, 2));

        float mn_lo = fmaxf(m_lo, mx_lo);
        float mn_hi = fmaxf(m_hi, mx_hi);
        float al_lo = __expf(m_lo - mn_lo);
        float al_hi = __expf(m_hi - mn_hi);
        m_lo = mn_lo; m_hi = mn_hi;

        float sum_lo = 0.0f, sum_hi = 0.0f;
#pragma unroll
        for (int j = 0; j < 8; j++) {
            float p0 = __expf(s[j][0] - mn_lo);
            float p1 = __expf(s[j][1] - mn_lo);
            float p2 = __expf(s[j][2] - mn_hi);
            float p3 = __expf(s[j][3] - mn_hi);
            sum_lo += p0 + p1;
            sum_hi += p2 + p3;
            s[j][0] = p0; s[j][1] = p1; s[j][2] = p2; s[j][3] = p3;
        }
        sum_lo += __shfl_xor_sync(FULL, sum_lo, 1);
        sum_lo += __shfl_xor_sync(FULL, sum_lo, 2);
        sum_hi += __shfl_xor_sync(FULL, sum_hi, 1);
        sum_hi += __shfl_xor_sync(FULL, sum_hi, 2);
        l_lo = l_lo * al_lo + sum_lo;
        l_hi = l_hi * al_hi + sum_hi;

#pragma unroll
        for (int j = 0; j < 8; j++) {
            o[j][0] *= al_lo; o[j][1] *= al_lo;
            o[j][2] *= al_hi; o[j][3] *= al_hi;
        }

        // ---- O += P @ V : fp16 A-frag == C-layout pairing, NO shuffles ----
#pragma unroll
        for (int kc = 0; kc < 4; kc++) {
            unsigned pa[4];
            pa[0] = pack_h2(s[2 * kc][0],     s[2 * kc][1]);
            pa[1] = pack_h2(s[2 * kc][2],     s[2 * kc][3]);
            pa[2] = pack_h2(s[2 * kc + 1][0], s[2 * kc + 1][1]);
            pa[3] = pack_h2(s[2 * kc + 1][2], s[2 * kc + 1][3]);
            int kh = kc * 16;
#pragma unroll
            for (int jn = 0; jn < 8; jn++) {
                int vr = (jn * 8 + g) * KSTR;
                unsigned b0 = *(const unsigned*)(Vts + vr + kh + 2 * tig);
                unsigned b1 = *(const unsigned*)(Vts + vr + kh + 8 + 2 * tig);
                mma_f16(o[jn], pa, b0, b1);
            }
        }
        __syncthreads();   // all warps done with Vts

        if (kt + 1 < NT) {
            const __half* Vp = Vtbase + (size_t)(kt + 1) * AKV;
#pragma unroll
            for (int i = 0; i < 4; i++) {
                int idx = i * 128 + tid;
                int r = idx >> 3, seg = idx & 7;
                cp_async16((char*)Vts + r * (KSTR * 2) + seg * 16,
                           Vp + (size_t)r * S_ + seg * 8);
            }
            asm volatile("cp.async.commit_group;");
        }
    }

    // ---- Normalize + write fp16 to [B,S,D] ----
    float inv_lo = 1.0f / l_lo;
    float inv_hi = 1.0f / l_hi;
    int b = bh / H_, h = bh % H_;
    __half* orow_lo = Ob + ((size_t)(b * S_ + qrow0 + g)) * D_ + h * HD_;
    __half* orow_hi = Ob + ((size_t)(b * S_ + qrow0 + g + 8)) * D_ + h * HD_;
#pragma unroll
    for (int jn = 0; jn < 8; jn++) {
        *(__half2*)(orow_lo + jn * 8 + 2 * tig)
            = __floats2half2_rn(o[jn][0] * inv_lo, o[jn][1] * inv_lo);
        *(__half2*)(orow_hi + jn * 8 + 2 * tig)
            = __floats2half2_rn(o[jn][2] * inv_hi, o[jn][3] * inv_hi);
    }
}

// ---------------------------------------------------------------------------
// Launch
// ---------------------------------------------------------------------------
extern "C" void kernel_launch(void* const* d_in, const int* in_sizes, int n_in,
                              void* d_out, int out_size)
{
    (void)in_sizes; (void)n_in; (void)out_size;
    const float* x  = (const float*)d_in[0];
    const float* Wq = (const float*)d_in[1];
    const float* bq = (const float*)d_in[2];
    const float* Wk = (const float*)d_in[3];
    const float* bk = (const float*)d_in[4];
    const float* Wv = (const float*)d_in[5];
    const float* bv = (const float*)d_in[6];
    const float* Wo = (const float*)d_in[7];
    const float* bo = (const float*)d_in[8];
    float* out = (float*)d_out;

    void *pq, *pk, *pv, *patt, *pxt, *pwt;
    cudaGetSymbolAddress(&pq, g_q);
    cudaGetSymbolAddress(&pk, g_k);
    cudaGetSymbolAddress(&pv, g_v);
    cudaGetSymbolAddress(&patt, g_att);
    cudaGetSymbolAddress(&pxt, g_xt);
    cudaGetSymbolAddress(&pwt, g_wt);
    __half* qb = (__half*)pq;
    __half* kb = (__half*)pk;
    __half* vb = (__half*)pv;
    __half* ab = (__half*)patt;
    __half* xt = (__half*)pxt;
    __half* wt = (__half*)pwt;

    cudaFuncSetAttribute(gemm_f16_kernel,
                         cudaFuncAttributeMaxDynamicSharedMemorySize, GSMB);

    // 1) Prep
    xcvt_kernel<<<M_TOT * D_ / 4 / 256, 256>>>(x, xt);
    wtrans_kernel<<<dim3(32, 32, 4), dim3(32, 8)>>>(Wq, Wk, Wv, Wo, wt);

    // 2) QKV projections (fp16 HMMA)
    dim3 ggrid(D_ / 128, M_TOT / 128);            // (8, 32)
    gemm_f16_kernel<<<ggrid, 256, GSMB>>>(xt, wt + 0 * (size_t)D_ * D_, bq, qb, 1, 0.125f);
    gemm_f16_kernel<<<ggrid, 256, GSMB>>>(xt, wt + 1 * (size_t)D_ * D_, bk, kb, 1, 1.0f);
    gemm_f16_kernel<<<ggrid, 256, GSMB>>>(xt, wt + 2 * (size_t)D_ * D_, bv, vb, 2, 1.0f);

    // 3) Attention
    dim3 agrid(S_ / AQ, B_ * H_);                 // (32, 32)
    attn_kernel<<<agrid, 128>>>(qb, kb, vb, ab);

    // 4) Output projection (fp16 A input, fp32 output)
    gemm_f16_kernel<<<ggrid, 256, GSMB>>>(ab, wt + 3 * (size_t)D_ * D_, bo, out, 0, 1.0f);
}

// round 12
// speedup vs baseline: 2.7621x; 1.0941x over previous
#include <cuda_runtime.h>
#include <cuda_fp16.h>
#include <cstdint>

// Problem constants (fixed shapes)
#define B_   2
#define S_   2048
#define D_   1024
#define H_   16
#define HD_  64
#define M_TOT (B_ * S_)   // 4096

// ---------------------------------------------------------------------------
// Scratch buffers (fp16; Q pre-scaled by 1/sqrt(HD); V stored TRANSPOSED)
// ---------------------------------------------------------------------------
__device__ __half g_q[B_ * H_ * S_ * HD_];    // [B,H,S,HD]
__device__ __half g_k[B_ * H_ * S_ * HD_];    // [B,H,S,HD]
__device__ __half g_v[B_ * H_ * S_ * HD_];    // [B,H,HD,S]  (transposed!)
__device__ __half g_att[B_ * S_ * D_];        // [B,S,D]
__device__ __half g_xt[M_TOT * D_];           // x in fp16 [M,K]
__device__ __half g_wt[4 * D_ * D_];          // W^T fp16 [N,K] x4

// ---------------------------------------------------------------------------
// Helpers
// ---------------------------------------------------------------------------
__device__ __forceinline__ void mma_f16(float* d, const unsigned* a,
                                        unsigned b0, unsigned b1) {
    asm volatile(
        "mma.sync.aligned.m16n8k16.row.col.f32.f16.f16.f32 "
        "{%0,%1,%2,%3}, {%4,%5,%6,%7}, {%8,%9}, {%0,%1,%2,%3};"
        : "+f"(d[0]), "+f"(d[1]), "+f"(d[2]), "+f"(d[3])
        : "r"(a[0]), "r"(a[1]), "r"(a[2]), "r"(a[3]), "r"(b0), "r"(b1));
}

__device__ __forceinline__ void cp_async16(void* smem_dst, const void* gmem_src) {
    unsigned saddr = (unsigned)__cvta_generic_to_shared(smem_dst);
    asm volatile("cp.async.cg.shared.global [%0], [%1], 16;"
                 :: "r"(saddr), "l"(gmem_src));
}

__device__ __forceinline__ unsigned pack_h2(float lo, float hi) {
    __half2 h = __floats2half2_rn(lo, hi);
    return *reinterpret_cast<unsigned*>(&h);
}

__device__ __forceinline__ void ldsm_x4(unsigned& d0, unsigned& d1,
                                        unsigned& d2, unsigned& d3,
                                        uint32_t addr) {
    asm volatile("ldmatrix.sync.aligned.m8n8.x4.shared.b16 {%0,%1,%2,%3}, [%4];"
                 : "=r"(d0), "=r"(d1), "=r"(d2), "=r"(d3) : "r"(addr));
}

__device__ __forceinline__ uint32_t smem_u32(const void* p) {
    return (uint32_t)__cvta_generic_to_shared(p);
}

// ---------------------------------------------------------------------------
// Prep: x -> fp16; W -> W^T fp16 [N,K]
// ---------------------------------------------------------------------------
__global__ void __launch_bounds__(256) xcvt_kernel(const float* __restrict__ x,
                                                   __half* __restrict__ xt) {
    int i = blockIdx.x * 256 + threadIdx.x;
    float4 v = ((const float4*)x)[i];
    ((__half2*)xt)[2 * i]     = __floats2half2_rn(v.x, v.y);
    ((__half2*)xt)[2 * i + 1] = __floats2half2_rn(v.z, v.w);
}

__global__ void wtrans_kernel(const float* __restrict__ wq,
                              const float* __restrict__ wk,
                              const float* __restrict__ wv,
                              const float* __restrict__ wo,
                              __half* __restrict__ wt) {
    __shared__ float tile[32][33];
    int w = blockIdx.z;
    const float* src = (w == 0) ? wq : (w == 1) ? wk : (w == 2) ? wv : wo;
    __half* dst = wt + (size_t)w * D_ * D_;
    int k0 = blockIdx.y * 32, n0 = blockIdx.x * 32;
    int tx = threadIdx.x, ty = threadIdx.y;
#pragma unroll
    for (int j = 0; j < 32; j += 8)
        tile[ty + j][tx] = src[(size_t)(k0 + ty + j) * D_ + n0 + tx];
    __syncthreads();
#pragma unroll
    for (int j = 0; j < 32; j += 8)
        dst[(size_t)(n0 + ty + j) * D_ + k0 + tx] = __float2half(tile[tx][ty + j]);
}

// ---------------------------------------------------------------------------
// FP16 GEMM with ldmatrix fragment loads. CTA 128x128, K-tile 64 halfs,
// 3-stage cp.async ring, warp tile 64x32, mma.m16n8k16.
// mode 0: fp32 [M,N]; mode 1: fp16 scatter [B,H,S,HD]; mode 2: fp16 [B,H,HD,S]
// ---------------------------------------------------------------------------
#define GSTR 72
#define ABYTES (128 * GSTR * 2)
#define STAGEB (2 * ABYTES)
#define GSMB (3 * STAGEB)

extern __shared__ char tsm[];

#define GEMM_ISSUE(t)                                                        \
    do {                                                                     \
        char* sbase = tsm + ((t) % 3) * STAGEB;                              \
        _Pragma("unroll")                                                    \
        for (int ii = 0; ii < 4; ii++) {                                     \
            int idx = ii * 256 + tid;                                        \
            int r = idx >> 3, seg = idx & 7;                                 \
            cp_async16(sbase + r * (GSTR * 2) + seg * 16,                    \
                       Ag + (size_t)r * D_ + (t) * 64 + seg * 8);            \
            cp_async16(sbase + ABYTES + r * (GSTR * 2) + seg * 16,           \
                       Bg + (size_t)r * D_ + (t) * 64 + seg * 8);            \
        }                                                                    \
        asm volatile("cp.async.commit_group;");                              \
    } while (0)

__global__ void __launch_bounds__(256, 2) gemm_f16_kernel(
    const __half* __restrict__ A, const __half* __restrict__ Wt,
    const float* __restrict__ bias, void* __restrict__ out,
    int mode, float oscale)
{
    const int tid  = threadIdx.x;
    const int warp = tid >> 5;
    const int lane = tid & 31;
    const int g    = lane >> 2;
    const int tig  = lane & 3;
    const int wm   = (warp >> 2) * 64;
    const int wn   = (warp & 3) * 32;
    const int bm   = blockIdx.y * 128;
    const int bn   = blockIdx.x * 128;

    const __half* Ag = A + (size_t)bm * D_;
    const __half* Bg = Wt + (size_t)bn * D_;

    // ldmatrix lane-offset components (in halfs)
    const int a_r = (lane & 7) + ((lane >> 3) & 1) * 8;   // row within 16-block
    const int a_c = (lane >> 4) * 8;                      // k-half select
    const int b_r = (lane & 7) + ((lane >> 4) & 1) * 8;   // n within 16-block
    const int b_c = ((lane >> 3) & 1) * 8;                // k-half select

    float acc[16][4];
#pragma unroll
    for (int f = 0; f < 16; f++)
#pragma unroll
        for (int e = 0; e < 4; e++) acc[f][e] = 0.0f;

    const uint32_t sb = smem_u32(tsm);
    const int NT = D_ / 64;          // 16
    GEMM_ISSUE(0);
    GEMM_ISSUE(1);

    for (int t = 0; t < NT; t++) {
        if (t < NT - 1) asm volatile("cp.async.wait_group 1;");
        else            asm volatile("cp.async.wait_group 0;");
        __syncthreads();

        if (t + 2 < NT) GEMM_ISSUE(t + 2);

        uint32_t abase = sb + (t % 3) * STAGEB
                       + (uint32_t)(((wm + a_r) * GSTR + a_c) * 2);
        uint32_t bbase = sb + (t % 3) * STAGEB + ABYTES
                       + (uint32_t)(((wn + b_r) * GSTR + b_c) * 2);

#pragma unroll
        for (int ks = 0; ks < 4; ks++) {
            uint32_t ka = abase + ks * 32;   // +16 halfs
            uint32_t kb = bbase + ks * 32;
            unsigned af[4][4];
#pragma unroll
            for (int i = 0; i < 4; i++)
                ldsm_x4(af[i][0], af[i][1], af[i][2], af[i][3],
                        ka + i * 16 * GSTR * 2);
            unsigned bf[4][2];
#pragma unroll
            for (int jp = 0; jp < 2; jp++)
                ldsm_x4(bf[2 * jp][0], bf[2 * jp][1],
                        bf[2 * jp + 1][0], bf[2 * jp + 1][1],
                        kb + jp * 16 * GSTR * 2);
#pragma unroll
            for (int i = 0; i < 4; i++)
#pragma unroll
                for (int j = 0; j < 4; j++)
                    mma_f16(acc[i * 4 + j], af[i], bf[j][0], bf[j][1]);
        }
    }

    // ---- Epilogue ----
#pragma unroll
    for (int i = 0; i < 4; i++) {
#pragma unroll
        for (int j = 0; j < 4; j++) {
            const float* d = acc[i * 4 + j];
            int col = bn + wn + j * 8 + 2 * tig;
            float2 b2 = *(const float2*)(bias + col);
            int row_lo = bm + wm + i * 16 + g;
            int row_hi = row_lo + 8;
            float2 vlo = { (d[0] + b2.x) * oscale, (d[1] + b2.y) * oscale };
            float2 vhi = { (d[2] + b2.x) * oscale, (d[3] + b2.y) * oscale };
            if (mode == 0) {
                float* of = (float*)out;
                *(float2*)(of + (size_t)row_lo * D_ + col) = vlo;
                *(float2*)(of + (size_t)row_hi * D_ + col) = vhi;
            } else if (mode == 1) {
                __half* oh = (__half*)out;
                int h = col / HD_, dd = col % HD_;
                int b0i = row_lo / S_, s0 = row_lo % S_;
                int b1i = row_hi / S_, s1 = row_hi % S_;
                *(__half2*)(oh + ((size_t)((b0i * H_ + h) * S_ + s0)) * HD_ + dd)
                    = __floats2half2_rn(vlo.x, vlo.y);
                *(__half2*)(oh + ((size_t)((b1i * H_ + h) * S_ + s1)) * HD_ + dd)
                    = __floats2half2_rn(vhi.x, vhi.y);
            } else {
                __half* oh = (__half*)out;
                int h = col / HD_, dd = col % HD_;
                int b0i = row_lo / S_, s0 = row_lo % S_;
                int b1i = row_hi / S_, s1 = row_hi % S_;
                oh[((size_t)((b0i * H_ + h) * HD_ + dd)) * S_ + s0]     = __float2half(vlo.x);
                oh[((size_t)((b0i * H_ + h) * HD_ + dd + 1)) * S_ + s0] = __float2half(vlo.y);
                oh[((size_t)((b1i * H_ + h) * HD_ + dd)) * S_ + s1]     = __float2half(vhi.x);
                oh[((size_t)((b1i * H_ + h) * HD_ + dd + 1)) * S_ + s1] = __float2half(vhi.y);
            }
        }
    }
}

// ---------------------------------------------------------------------------
// Flash attention fp16 + ldmatrix: register S/P/O, mma.m16n8k16, zero
// shuffles. K double-buffered, Vt single-buffered.
// ---------------------------------------------------------------------------
#define AKV 64
#define AQ  64
#define KSTR 72

__global__ void __launch_bounds__(128, 4) attn_kernel(
    const __half* __restrict__ Qb, const __half* __restrict__ Kb,
    const __half* __restrict__ Vtb, __half* __restrict__ Ob)
{
    __shared__ __half Ks0[64 * KSTR];
    __shared__ __half Ks1[64 * KSTR];
    __shared__ __half Vts[64 * KSTR];

    const int bh   = blockIdx.y;
    const int qt   = blockIdx.x;
    const int tid  = threadIdx.x;
    const int warp = tid >> 5;
    const int lane = tid & 31;
    const int g    = lane >> 2;
    const int tig  = lane & 3;

    const int b_r = (lane & 7) + ((lane >> 4) & 1) * 8;
    const int b_c = ((lane >> 3) & 1) * 8;

    const __half* Kbase  = Kb + (size_t)bh * S_ * HD_;
    const __half* Vtbase = Vtb + (size_t)bh * HD_ * S_;

    {
#pragma unroll
        for (int i = 0; i < 4; i++) {
            int idx = i * 128 + tid;
            int r = idx >> 3, seg = idx & 7;
            cp_async16((char*)Ks0 + r * (KSTR * 2) + seg * 16,
                       Kbase + (size_t)r * HD_ + seg * 8);
            cp_async16((char*)Vts + r * (KSTR * 2) + seg * 16,
                       Vtbase + (size_t)r * S_ + seg * 8);
        }
        asm volatile("cp.async.commit_group;");
    }

    const int qrow0 = qt * AQ + warp * 16;
    const __half* Qp = Qb + ((size_t)bh * S_ + qrow0) * HD_;
    unsigned qa[4][4];
#pragma unroll
    for (int kc = 0; kc < 4; kc++) {
        int kh = kc * 16;
        qa[kc][0] = *(const unsigned*)(Qp + (size_t)g * HD_ + kh + 2 * tig);
        qa[kc][1] = *(const unsigned*)(Qp + (size_t)(g + 8) * HD_ + kh + 2 * tig);
        qa[kc][2] = *(const unsigned*)(Qp + (size_t)g * HD_ + kh + 8 + 2 * tig);
        qa[kc][3] = *(const unsigned*)(Qp + (size_t)(g + 8) * HD_ + kh + 8 + 2 * tig);
    }

    const uint32_t ks0b = smem_u32(Ks0) + (uint32_t)((b_r * KSTR + b_c) * 2);
    const uint32_t ks1b = smem_u32(Ks1) + (uint32_t)((b_r * KSTR + b_c) * 2);
    const uint32_t vtsb = smem_u32(Vts) + (uint32_t)((b_r * KSTR + b_c) * 2);

    float o[8][4];
#pragma unroll
    for (int j = 0; j < 8; j++)
#pragma unroll
        for (int e = 0; e < 4; e++) o[j][e] = 0.0f;
    float m_lo = -1e30f, m_hi = -1e30f;
    float l_lo = 0.0f,   l_hi = 0.0f;
    const unsigned FULL = 0xffffffffu;

    const int NT = S_ / AKV;
    for (int kt = 0; kt < NT; kt++) {
        if (kt + 1 < NT) {
            __half* Kd = ((kt + 1) & 1) ? Ks1 : Ks0;
            const __half* Kp = Kbase + (size_t)(kt + 1) * AKV * HD_;
#pragma unroll
            for (int i = 0; i < 4; i++) {
                int idx = i * 128 + tid;
                int r = idx >> 3, seg = idx & 7;
                cp_async16((char*)Kd + r * (KSTR * 2) + seg * 16,
                           Kp + (size_t)r * HD_ + seg * 8);
            }
            asm volatile("cp.async.commit_group;");
            asm volatile("cp.async.wait_group 1;");
        } else {
            asm volatile("cp.async.wait_group 0;");
        }
        __syncthreads();

        const uint32_t ksb = (kt & 1) ? ks1b : ks0b;

        // ---- S = Q @ K^T ----
        float s[8][4];
#pragma unroll
        for (int j = 0; j < 8; j++)
#pragma unroll
            for (int e = 0; e < 4; e++) s[j][e] = 0.0f;

#pragma unroll
        for (int kc = 0; kc < 4; kc++) {
            uint32_t ka = ksb + kc * 32;
#pragma unroll
            for (int jp = 0; jp < 4; jp++) {
                unsigned b00, b01, b10, b11;
                ldsm_x4(b00, b01, b10, b11, ka + jp * 16 * KSTR * 2);
                mma_f16(s[2 * jp],     qa[kc], b00, b01);
                mma_f16(s[2 * jp + 1], qa[kc], b10, b11);
            }
        }

        // ---- Online softmax ----
        float mx_lo = -1e30f, mx_hi = -1e30f;
#pragma unroll
        for (int j = 0; j < 8; j++) {
            mx_lo = fmaxf(mx_lo, fmaxf(s[j][0], s[j][1]));
            mx_hi = fmaxf(mx_hi, fmaxf(s[j][2], s[j][3]));
        }
        mx_lo = fmaxf(mx_lo, __shfl_xor_sync(FULL, mx_lo, 1));
        mx_lo = fmaxf(mx_lo, __shfl_xor_sync(FULL, mx_lo, 2));
        mx_hi = fmaxf(mx_hi, __shfl_xor_sync(FULL, mx_hi, 1));
        mx_hi = fmaxf(mx_hi, __shfl_xor_sync(FULL, mx_hi, 2));

        float mn_lo = fmaxf(m_lo, mx_lo);
        float mn_hi = fmaxf(m_hi, mx_hi);
        float al_lo = __expf(m_lo - mn_lo);
        float al_hi = __expf(m_hi - mn_hi);
        m_lo = mn_lo; m_hi = mn_hi;

        float sum_lo = 0.0f, sum_hi = 0.0f;
#pragma unroll
        for (int j = 0; j < 8; j++) {
            float p0 = __expf(s[j][0] - mn_lo);
            float p1 = __expf(s[j][1] - mn_lo);
            float p2 = __expf(s[j][2] - mn_hi);
            float p3 = __expf(s[j][3] - mn_hi);
            sum_lo += p0 + p1;
            sum_hi += p2 + p3;
            s[j][0] = p0; s[j][1] = p1; s[j][2] = p2; s[j][3] = p3;
        }
        sum_lo += __shfl_xor_sync(FULL, sum_lo, 1);
        sum_lo += __shfl_xor_sync(FULL, sum_lo, 2);
        sum_hi += __shfl_xor_sync(FULL, sum_hi, 1);
        sum_hi += __shfl_xor_sync(FULL, sum_hi, 2);
        l_lo = l_lo * al_lo + sum_lo;
        l_hi = l_hi * al_hi + sum_hi;

#pragma unroll
        for (int j = 0; j < 8; j++) {
            o[j][0] *= al_lo; o[j][1] *= al_lo;
            o[j][2] *= al_hi; o[j][3] *= al_hi;
        }

        // ---- O += P @ V (A-frag = packed C, no shuffles) ----
#pragma unroll
        for (int kc = 0; kc < 4; kc++) {
            unsigned pa[4];
            pa[0] = pack_h2(s[2 * kc][0],     s[2 * kc][1]);
            pa[1] = pack_h2(s[2 * kc][2],     s[2 * kc][3]);
            pa[2] = pack_h2(s[2 * kc + 1][0], s[2 * kc + 1][1]);
            pa[3] = pack_h2(s[2 * kc + 1][2], s[2 * kc + 1][3]);
            uint32_t ka = vtsb + kc * 32;
#pragma unroll
            for (int jp = 0; jp < 4; jp++) {
                unsigned b00, b01, b10, b11;
                ldsm_x4(b00, b01, b10, b11, ka + jp * 16 * KSTR * 2);
                mma_f16(o[2 * jp],     pa, b00, b01);
                mma_f16(o[2 * jp + 1], pa, b10, b11);
            }
        }
        __syncthreads();

        if (kt + 1 < NT) {
            const __half* Vp = Vtbase + (size_t)(kt + 1) * AKV;
#pragma unroll
            for (int i = 0; i < 4; i++) {
                int idx = i * 128 + tid;
                int r = idx >> 3, seg = idx & 7;
                cp_async16((char*)Vts + r * (KSTR * 2) + seg * 16,
                           Vp + (size_t)r * S_ + seg * 8);
            }
            asm volatile("cp.async.commit_group;");
        }
    }

    // ---- Normalize + write fp16 to [B,S,D] ----
    float inv_lo = 1.0f / l_lo;
    float inv_hi = 1.0f / l_hi;
    int b = bh / H_, h = bh % H_;
    __half* orow_lo = Ob + ((size_t)(b * S_ + qrow0 + g)) * D_ + h * HD_;
    __half* orow_hi = Ob + ((size_t)(b * S_ + qrow0 + g + 8)) * D_ + h * HD_;
#pragma unroll
    for (int jn = 0; jn < 8; jn++) {
        *(__half2*)(orow_lo + jn * 8 + 2 * tig)
            = __floats2half2_rn(o[jn][0] * inv_lo, o[jn][1] * inv_lo);
        *(__half2*)(orow_hi + jn * 8 + 2 * tig)
            = __floats2half2_rn(o[jn][2] * inv_hi, o[jn][3] * inv_hi);
    }
}

// ---------------------------------------------------------------------------
// Launch
// ---------------------------------------------------------------------------
extern "C" void kernel_launch(void* const* d_in, const int* in_sizes, int n_in,
                              void* d_out, int out_size)
{
    (void)in_sizes; (void)n_in; (void)out_size;
    const float* x  = (const float*)d_in[0];
    const float* Wq = (const float*)d_in[1];
    const float* bq = (const float*)d_in[2];
    const float* Wk = (const float*)d_in[3];
    const float* bk = (const float*)d_in[4];
    const float* Wv = (const float*)d_in[5];
    const float* bv = (const float*)d_in[6];
    const float* Wo = (const float*)d_in[7];
    const float* bo = (const float*)d_in[8];
    float* out = (float*)d_out;

    void *pq, *pk, *pv, *patt, *pxt, *pwt;
    cudaGetSymbolAddress(&pq, g_q);
    cudaGetSymbolAddress(&pk, g_k);
    cudaGetSymbolAddress(&pv, g_v);
    cudaGetSymbolAddress(&patt, g_att);
    cudaGetSymbolAddress(&pxt, g_xt);
    cudaGetSymbolAddress(&pwt, g_wt);
    __half* qb = (__half*)pq;
    __half* kb = (__half*)pk;
    __half* vb = (__half*)pv;
    __half* ab = (__half*)patt;
    __half* xt = (__half*)pxt;
    __half* wt = (__half*)pwt;

    cudaFuncSetAttribute(gemm_f16_kernel,
                         cudaFuncAttributeMaxDynamicSharedMemorySize, GSMB);

    // 1) Prep
    xcvt_kernel<<<M_TOT * D_ / 4 / 256, 256>>>(x, xt);
    wtrans_kernel<<<dim3(32, 32, 4), dim3(32, 8)>>>(Wq, Wk, Wv, Wo, wt);

    // 2) QKV projections
    dim3 ggrid(D_ / 128, M_TOT / 128);            // (8, 32)
    gemm_f16_kernel<<<ggrid, 256, GSMB>>>(xt, wt + 0 * (size_t)D_ * D_, bq, qb, 1, 0.125f);
    gemm_f16_kernel<<<ggrid, 256, GSMB>>>(xt, wt + 1 * (size_t)D_ * D_, bk, kb, 1, 1.0f);
    gemm_f16_kernel<<<ggrid, 256, GSMB>>>(xt, wt + 2 * (size_t)D_ * D_, bv, vb, 2, 1.0f);

    // 3) Attention
    dim3 agrid(S_ / AQ, B_ * H_);                 // (32, 32)
    attn_kernel<<<agrid, 128>>>(qb, kb, vb, ab);

    // 4) Output projection
    gemm_f16_kernel<<<ggrid, 256, GSMB>>>(ab, wt + 3 * (size_t)D_ * D_, bo, out, 0, 1.0f);
}

// round 13
// speedup vs baseline: 2.8065x; 1.0161x over previous
#include <cuda_runtime.h>
#include <cuda_fp16.h>
#include <cstdint>

// Problem constants (fixed shapes)
#define B_   2
#define S_   2048
#define D_   1024
#define H_   16
#define HD_  64
#define M_TOT (B_ * S_)   // 4096

// ---------------------------------------------------------------------------
// Scratch buffers (fp16; Q pre-scaled by 1/sqrt(HD); all natural layouts)
// ---------------------------------------------------------------------------
__device__ __half g_q[B_ * H_ * S_ * HD_];    // [B,H,S,HD]
__device__ __half g_k[B_ * H_ * S_ * HD_];    // [B,H,S,HD]
__device__ __half g_v[B_ * H_ * S_ * HD_];    // [B,H,S,HD]
__device__ __half g_att[B_ * S_ * D_];        // [B,S,D]
__device__ __half g_xt[M_TOT * D_];           // x fp16 [M,K]
__device__ __half g_wt[4 * D_ * D_];          // W fp16 [K,N] x4 (NO transpose)

// ---------------------------------------------------------------------------
// Helpers
// ---------------------------------------------------------------------------
__device__ __forceinline__ void mma_f16(float* d, const unsigned* a,
                                        unsigned b0, unsigned b1) {
    asm volatile(
        "mma.sync.aligned.m16n8k16.row.col.f32.f16.f16.f32 "
        "{%0,%1,%2,%3}, {%4,%5,%6,%7}, {%8,%9}, {%0,%1,%2,%3};"
        : "+f"(d[0]), "+f"(d[1]), "+f"(d[2]), "+f"(d[3])
        : "r"(a[0]), "r"(a[1]), "r"(a[2]), "r"(a[3]), "r"(b0), "r"(b1));
}

__device__ __forceinline__ void cp_async16(void* smem_dst, const void* gmem_src) {
    unsigned saddr = (unsigned)__cvta_generic_to_shared(smem_dst);
    asm volatile("cp.async.cg.shared.global [%0], [%1], 16;"
                 :: "r"(saddr), "l"(gmem_src));
}

__device__ __forceinline__ unsigned pack_h2(float lo, float hi) {
    __half2 h = __floats2half2_rn(lo, hi);
    return *reinterpret_cast<unsigned*>(&h);
}

__device__ __forceinline__ void ldsm_x4(unsigned& d0, unsigned& d1,
                                        unsigned& d2, unsigned& d3,
                                        uint32_t addr) {
    asm volatile("ldmatrix.sync.aligned.m8n8.x4.shared.b16 {%0,%1,%2,%3}, [%4];"
                 : "=r"(d0), "=r"(d1), "=r"(d2), "=r"(d3) : "r"(addr));
}

__device__ __forceinline__ void ldsm_x4_t(unsigned& d0, unsigned& d1,
                                          unsigned& d2, unsigned& d3,
                                          uint32_t addr) {
    asm volatile("ldmatrix.sync.aligned.m8n8.x4.trans.shared.b16 {%0,%1,%2,%3}, [%4];"
                 : "=r"(d0), "=r"(d1), "=r"(d2), "=r"(d3) : "r"(addr));
}

__device__ __forceinline__ uint32_t smem_u32(const void* p) {
    return (uint32_t)__cvta_generic_to_shared(p);
}

// ---------------------------------------------------------------------------
// Prep: x AND all W -> fp16 (pure elementwise, one kernel, no transpose)
// ---------------------------------------------------------------------------
#define XN4 (M_TOT * D_ / 4)       // 1048576
#define WN4 (D_ * D_ / 4)          // 262144 each

__global__ void __launch_bounds__(256) cvt_all_kernel(
    const float* __restrict__ x,
    const float* __restrict__ wq, const float* __restrict__ wk,
    const float* __restrict__ wv, const float* __restrict__ wo,
    __half* __restrict__ xt, __half* __restrict__ wt)
{
    int i = blockIdx.x * 256 + threadIdx.x;
    const float4* s;
    __half2* d;
    if (i < XN4) {
        s = (const float4*)x + i;
        d = (__half2*)xt + 2 * i;
    } else {
        int j = i - XN4;
        int w = j >> 18;
        int off = j & (WN4 - 1);
        const float* ws = (w == 0) ? wq : (w == 1) ? wk : (w == 2) ? wv : wo;
        s = (const float4*)ws + off;
        d = (__half2*)(wt + (size_t)w * D_ * D_) + 2 * off;
    }
    float4 v = *s;
    d[0] = __floats2half2_rn(v.x, v.y);
    d[1] = __floats2half2_rn(v.z, v.w);
}

// ---------------------------------------------------------------------------
// FP16 GEMM: out = A[M,K] @ W[K,N] + bias. B-fragments via ldmatrix.trans
// from NATURAL [K,N] W. CTA 128x128, K-tile 64, 3-stage cp.async ring.
// mode 0: fp32 [M,N]; mode 1: fp16 scatter [B,H,S,HD].
// ---------------------------------------------------------------------------
#define GSTR 72                      // A smem row stride (halfs)
#define BSTR 136                     // B smem row stride (halfs), 128+8
#define ABYT (128 * GSTR * 2)        // 18432
#define BBYT (64 * BSTR * 2)         // 17408
#define STAGEB (ABYT + BBYT)         // 35840
#define GSMB (3 * STAGEB)            // 107520

extern __shared__ char tsm[];

#define GEMM_ISSUE(t)                                                        \
    do {                                                                     \
        char* sbase = tsm + ((t) % 3) * STAGEB;                              \
        _Pragma("unroll")                                                    \
        for (int ii = 0; ii < 4; ii++) {                                     \
            int idx = ii * 256 + tid;                                        \
            int ra = idx >> 3, sa = idx & 7;                                 \
            cp_async16(sbase + ra * (GSTR * 2) + sa * 16,                    \
                       Ag + (size_t)ra * D_ + (t) * 64 + sa * 8);            \
            int rb = idx >> 4, sg = idx & 15;                                \
            cp_async16(sbase + ABYT + rb * (BSTR * 2) + sg * 16,             \
                       Bg + (size_t)((t) * 64 + rb) * D_ + sg * 8);          \
        }                                                                    \
        asm volatile("cp.async.commit_group;");                              \
    } while (0)

__global__ void __launch_bounds__(256, 2) gemm_f16_kernel(
    const __half* __restrict__ A, const __half* __restrict__ W,
    const float* __restrict__ bias, void* __restrict__ out,
    int mode, float oscale)
{
    const int tid  = threadIdx.x;
    const int warp = tid >> 5;
    const int lane = tid & 31;
    const int g    = lane >> 2;
    const int tig  = lane & 3;
    const int wm   = (warp >> 2) * 64;
    const int wn   = (warp & 3) * 32;
    const int bm   = blockIdx.y * 128;
    const int bn   = blockIdx.x * 128;

    const __half* Ag = A + (size_t)bm * D_;
    const __half* Bg = W + bn;

    // A ldmatrix lane offsets
    const int a_r = (lane & 7) + ((lane >> 3) & 1) * 8;
    const int a_c = (lane >> 4) * 8;
    // B trans-ldmatrix lane offsets: k within 16, n-block within 16
    const int kb_r = (lane & 7) + ((lane >> 3) & 1) * 8;
    const int kb_n = (lane >> 4) * 8;

    float acc[16][4];
#pragma unroll
    for (int f = 0; f < 16; f++)
#pragma unroll
        for (int e = 0; e < 4; e++) acc[f][e] = 0.0f;

    const uint32_t sb = smem_u32(tsm);
    const int NT = D_ / 64;          // 16
    GEMM_ISSUE(0);
    GEMM_ISSUE(1);

    for (int t = 0; t < NT; t++) {
        if (t < NT - 1) asm volatile("cp.async.wait_group 1;");
        else            asm volatile("cp.async.wait_group 0;");
        __syncthreads();

        if (t + 2 < NT) GEMM_ISSUE(t + 2);

        uint32_t abase = sb + (t % 3) * STAGEB
                       + (uint32_t)(((wm + a_r) * GSTR + a_c) * 2);
        uint32_t bbase = sb + (t % 3) * STAGEB + ABYT
                       + (uint32_t)((kb_r * BSTR + wn + kb_n) * 2);

#pragma unroll
        for (int ks = 0; ks < 4; ks++) {
            unsigned af[4][4];
#pragma unroll
            for (int i = 0; i < 4; i++)
                ldsm_x4(af[i][0], af[i][1], af[i][2], af[i][3],
                        abase + ks * 32 + i * 16 * GSTR * 2);
            unsigned bf[4][2];
#pragma unroll
            for (int jp = 0; jp < 2; jp++)
                ldsm_x4_t(bf[2 * jp][0], bf[2 * jp][1],
                          bf[2 * jp + 1][0], bf[2 * jp + 1][1],
                          bbase + ks * 16 * BSTR * 2 + jp * 32);
#pragma unroll
            for (int i = 0; i < 4; i++)
#pragma unroll
                for (int j = 0; j < 4; j++)
                    mma_f16(acc[i * 4 + j], af[i], bf[j][0], bf[j][1]);
        }
    }

    // ---- Epilogue ----
#pragma unroll
    for (int i = 0; i < 4; i++) {
#pragma unroll
        for (int j = 0; j < 4; j++) {
            const float* d = acc[i * 4 + j];
            int col = bn + wn + j * 8 + 2 * tig;
            float2 b2 = *(const float2*)(bias + col);
            int row_lo = bm + wm + i * 16 + g;
            int row_hi = row_lo + 8;
            float2 vlo = { (d[0] + b2.x) * oscale, (d[1] + b2.y) * oscale };
            float2 vhi = { (d[2] + b2.x) * oscale, (d[3] + b2.y) * oscale };
            if (mode == 0) {
                float* of = (float*)out;
                *(float2*)(of + (size_t)row_lo * D_ + col) = vlo;
                *(float2*)(of + (size_t)row_hi * D_ + col) = vhi;
            } else {
                __half* oh = (__half*)out;
                int h = col / HD_, dd = col % HD_;
                int b0i = row_lo / S_, s0 = row_lo % S_;
                int b1i = row_hi / S_, s1 = row_hi % S_;
                *(__half2*)(oh + ((size_t)((b0i * H_ + h) * S_ + s0)) * HD_ + dd)
                    = __floats2half2_rn(vlo.x, vlo.y);
                *(__half2*)(oh + ((size_t)((b1i * H_ + h) * S_ + s1)) * HD_ + dd)
                    = __floats2half2_rn(vhi.x, vhi.y);
            }
        }
    }
}

// ---------------------------------------------------------------------------
// Flash attention fp16: K via ldmatrix, V via ldmatrix.trans from NATURAL
// [S,HD] layout. Register S/P/O; K double-buffered, V single-buffered.
// ---------------------------------------------------------------------------
#define AKV 64
#define AQ  64
#define KSTR 72

__global__ void __launch_bounds__(128, 4) attn_kernel(
    const __half* __restrict__ Qb, const __half* __restrict__ Kb,
    const __half* __restrict__ Vb, __half* __restrict__ Ob)
{
    __shared__ __half Ks0[64 * KSTR];
    __shared__ __half Ks1[64 * KSTR];
    __shared__ __half Vts[64 * KSTR];

    const int bh   = blockIdx.y;
    const int qt   = blockIdx.x;
    const int tid  = threadIdx.x;
    const int warp = tid >> 5;
    const int lane = tid & 31;
    const int g    = lane >> 2;
    const int tig  = lane & 3;

    // K (non-trans): n=kv row, k-half select
    const int b_r = (lane & 7) + ((lane >> 4) & 1) * 8;
    const int b_c = ((lane >> 3) & 1) * 8;
    // V (trans): k=kv row within 16, n=hd block
    const int kb_r = (lane & 7) + ((lane >> 3) & 1) * 8;
    const int kb_n = (lane >> 4) * 8;

    const __half* Kbase = Kb + (size_t)bh * S_ * HD_;
    const __half* Vbase = Vb + (size_t)bh * S_ * HD_;

    {
#pragma unroll
        for (int i = 0; i < 4; i++) {
            int idx = i * 128 + tid;
            int r = idx >> 3, seg = idx & 7;
            cp_async16((char*)Ks0 + r * (KSTR * 2) + seg * 16,
                       Kbase + (size_t)r * HD_ + seg * 8);
            cp_async16((char*)Vts + r * (KSTR * 2) + seg * 16,
                       Vbase + (size_t)r * HD_ + seg * 8);
        }
        asm volatile("cp.async.commit_group;");
    }

    const int qrow0 = qt * AQ + warp * 16;
    const __half* Qp = Qb + ((size_t)bh * S_ + qrow0) * HD_;
    unsigned qa[4][4];
#pragma unroll
    for (int kc = 0; kc < 4; kc++) {
        int kh = kc * 16;
        qa[kc][0] = *(const unsigned*)(Qp + (size_t)g * HD_ + kh + 2 * tig);
        qa[kc][1] = *(const unsigned*)(Qp + (size_t)(g + 8) * HD_ + kh + 2 * tig);
        qa[kc][2] = *(const unsigned*)(Qp + (size_t)g * HD_ + kh + 8 + 2 * tig);
        qa[kc][3] = *(const unsigned*)(Qp + (size_t)(g + 8) * HD_ + kh + 8 + 2 * tig);
    }

    const uint32_t ks0b = smem_u32(Ks0) + (uint32_t)((b_r * KSTR + b_c) * 2);
    const uint32_t ks1b = smem_u32(Ks1) + (uint32_t)((b_r * KSTR + b_c) * 2);
    const uint32_t vtsb = smem_u32(Vts) + (uint32_t)((kb_r * KSTR + kb_n) * 2);

    float o[8][4];
#pragma unroll
    for (int j = 0; j < 8; j++)
#pragma unroll
        for (int e = 0; e < 4; e++) o[j][e] = 0.0f;
    float m_lo = -1e30f, m_hi = -1e30f;
    float l_lo = 0.0f,   l_hi = 0.0f;
    const unsigned FULL = 0xffffffffu;

    const int NT = S_ / AKV;
    for (int kt = 0; kt < NT; kt++) {
        if (kt + 1 < NT) {
            __half* Kd = ((kt + 1) & 1) ? Ks1 : Ks0;
            const __half* Kp = Kbase + (size_t)(kt + 1) * AKV * HD_;
#pragma unroll
            for (int i = 0; i < 4; i++) {
                int idx = i * 128 + tid;
                int r = idx >> 3, seg = idx & 7;
                cp_async16((char*)Kd + r * (KSTR * 2) + seg * 16,
                           Kp + (size_t)r * HD_ + seg * 8);
            }
            asm volatile("cp.async.commit_group;");
            asm volatile("cp.async.wait_group 1;");
        } else {
            asm volatile("cp.async.wait_group 0;");
        }
        __syncthreads();

        const uint32_t ksb = (kt & 1) ? ks1b : ks0b;

        // ---- S = Q @ K^T ----
        float s[8][4];
#pragma unroll
        for (int j = 0; j < 8; j++)
#pragma unroll
            for (int e = 0; e < 4; e++) s[j][e] = 0.0f;

#pragma unroll
        for (int kc = 0; kc < 4; kc++) {
            uint32_t ka = ksb + kc * 32;
#pragma unroll
            for (int jp = 0; jp < 4; jp++) {
                unsigned b00, b01, b10, b11;
                ldsm_x4(b00, b01, b10, b11, ka + jp * 16 * KSTR * 2);
                mma_f16(s[2 * jp],     qa[kc], b00, b01);
                mma_f16(s[2 * jp + 1], qa[kc], b10, b11);
            }
        }

        // ---- Online softmax ----
        float mx_lo = -1e30f, mx_hi = -1e30f;
#pragma unroll
        for (int j = 0; j < 8; j++) {
            mx_lo = fmaxf(mx_lo, fmaxf(s[j][0], s[j][1]));
            mx_hi = fmaxf(mx_hi, fmaxf(s[j][2], s[j][3]));
        }
        mx_lo = fmaxf(mx_lo, __shfl_xor_sync(FULL, mx_lo, 1));
        mx_lo = fmaxf(mx_lo, __shfl_xor_sync(FULL, mx_lo, 2));
        mx_hi = fmaxf(mx_hi, __shfl_xor_sync(FULL, mx_hi, 1));
        mx_hi = fmaxf(mx_hi, __shfl_xor_sync(FULL, mx_hi, 2));

        float mn_lo = fmaxf(m_lo, mx_lo);
        float mn_hi = fmaxf(m_hi, mx_hi);
        float al_lo = __expf(m_lo - mn_lo);
        float al_hi = __expf(m_hi - mn_hi);
        m_lo = mn_lo; m_hi = mn_hi;

        float sum_lo = 0.0f, sum_hi = 0.0f;
#pragma unroll
        for (int j = 0; j < 8; j++) {
            float p0 = __expf(s[j][0] - mn_lo);
            float p1 = __expf(s[j][1] - mn_lo);
            float p2 = __expf(s[j][2] - mn_hi);
            float p3 = __expf(s[j][3] - mn_hi);
            sum_lo += p0 + p1;
            sum_hi += p2 + p3;
            s[j][0] = p0; s[j][1] = p1; s[j][2] = p2; s[j][3] = p3;
        }
        sum_lo += __shfl_xor_sync(FULL, sum_lo, 1);
        sum_lo += __shfl_xor_sync(FULL, sum_lo, 2);
        sum_hi += __shfl_xor_sync(FULL, sum_hi, 1);
        sum_hi += __shfl_xor_sync(FULL, sum_hi, 2);
        l_lo = l_lo * al_lo + sum_lo;
        l_hi = l_hi * al_hi + sum_hi;

#pragma unroll
        for (int j = 0; j < 8; j++) {
            o[j][0] *= al_lo; o[j][1] *= al_lo;
            o[j][2] *= al_hi; o[j][3] *= al_hi;
        }

        // ---- O += P @ V (V natural layout, trans ldmatrix) ----
#pragma unroll
        for (int kc = 0; kc < 4; kc++) {
            unsigned pa[4];
            pa[0] = pack_h2(s[2 * kc][0],     s[2 * kc][1]);
            pa[1] = pack_h2(s[2 * kc][2],     s[2 * kc][3]);
            pa[2] = pack_h2(s[2 * kc + 1][0], s[2 * kc + 1][1]);
            pa[3] = pack_h2(s[2 * kc + 1][2], s[2 * kc + 1][3]);
            uint32_t ka = vtsb + kc * 16 * KSTR * 2;
#pragma unroll
            for (int jp = 0; jp < 4; jp++) {
                unsigned b00, b01, b10, b11;
                ldsm_x4_t(b00, b01, b10, b11, ka + jp * 32);
                mma_f16(o[2 * jp],     pa, b00, b01);
                mma_f16(o[2 * jp + 1], pa, b10, b11);
            }
        }
        __syncthreads();

        if (kt + 1 < NT) {
            const __half* Vp = Vbase + (size_t)(kt + 1) * AKV * HD_;
#pragma unroll
            for (int i = 0; i < 4; i++) {
                int idx = i * 128 + tid;
                int r = idx >> 3, seg = idx & 7;
                cp_async16((char*)Vts + r * (KSTR * 2) + seg * 16,
                           Vp + (size_t)r * HD_ + seg * 8);
            }
            asm volatile("cp.async.commit_group;");
        }
    }

    // ---- Normalize + write fp16 to [B,S,D] ----
    float inv_lo = 1.0f / l_lo;
    float inv_hi = 1.0f / l_hi;
    int b = bh / H_, h = bh % H_;
    __half* orow_lo = Ob + ((size_t)(b * S_ + qrow0 + g)) * D_ + h * HD_;
    __half* orow_hi = Ob + ((size_t)(b * S_ + qrow0 + g + 8)) * D_ + h * HD_;
#pragma unroll
    for (int jn = 0; jn < 8; jn++) {
        *(__half2*)(orow_lo + jn * 8 + 2 * tig)
            = __floats2half2_rn(o[jn][0] * inv_lo, o[jn][1] * inv_lo);
        *(__half2*)(orow_hi + jn * 8 + 2 * tig)
            = __floats2half2_rn(o[jn][2] * inv_hi, o[jn][3] * inv_hi);
    }
}

// ---------------------------------------------------------------------------
// Launch
// ---------------------------------------------------------------------------
extern "C" void kernel_launch(void* const* d_in, const int* in_sizes, int n_in,
                              void* d_out, int out_size)
{
    (void)in_sizes; (void)n_in; (void)out_size;
    const float* x  = (const float*)d_in[0];
    const float* Wq = (const float*)d_in[1];
    const float* bq = (const float*)d_in[2];
    const float* Wk = (const float*)d_in[3];
    const float* bk = (const float*)d_in[4];
    const float* Wv = (const float*)d_in[5];
    const float* bv = (const float*)d_in[6];
    const float* Wo = (const float*)d_in[7];
    const float* bo = (const float*)d_in[8];
    float* out = (float*)d_out;

    void *pq, *pk, *pv, *patt, *pxt, *pwt;
    cudaGetSymbolAddress(&pq, g_q);
    cudaGetSymbolAddress(&pk, g_k);
    cudaGetSymbolAddress(&pv, g_v);
    cudaGetSymbolAddress(&patt, g_att);
    cudaGetSymbolAddress(&pxt, g_xt);
    cudaGetSymbolAddress(&pwt, g_wt);
    __half* qb = (__half*)pq;
    __half* kb = (__half*)pk;
    __half* vb = (__half*)pv;
    __half* ab = (__half*)patt;
    __half* xt = (__half*)pxt;
    __half* wt = (__half*)pwt;

    cudaFuncSetAttribute(gemm_f16_kernel,
                         cudaFuncAttributeMaxDynamicSharedMemorySize, GSMB);

    // 1) Prep: elementwise fp32->fp16 for x and all W (no transpose)
    int nthr = XN4 + 4 * WN4;   // 2097152
    cvt_all_kernel<<<nthr / 256, 256>>>(x, Wq, Wk, Wv, Wo, xt, wt);

    // 2) QKV projections
    dim3 ggrid(D_ / 128, M_TOT / 128);            // (8, 32)
    gemm_f16_kernel<<<ggrid, 256, GSMB>>>(xt, wt + 0 * (size_t)D_ * D_, bq, qb, 1, 0.125f);
    gemm_f16_kernel<<<ggrid, 256, GSMB>>>(xt, wt + 1 * (size_t)D_ * D_, bk, kb, 1, 1.0f);
    gemm_f16_kernel<<<ggrid, 256, GSMB>>>(xt, wt + 2 * (size_t)D_ * D_, bv, vb, 1, 1.0f);

    // 3) Attention
    dim3 agrid(S_ / AQ, B_ * H_);                 // (32, 32)
    attn_kernel<<<agrid, 128>>>(qb, kb, vb, ab);

    // 4) Output projection
    gemm_f16_kernel<<<ggrid, 256, GSMB>>>(ab, wt + 3 * (size_t)D_ * D_, bo, out, 0, 1.0f);
}